// round 3
// baseline (speedup 1.0000x reference)
#include <cuda_runtime.h>
#include <cstdint>

// ---------------------------------------------------------------------------
// DAS beamformer — replicates XLA's compiled f32 chain:
//   m  = rn(rn(mask*1000) + 128)                       (separate mul/add, no FMA)
//   vx = rn(rn(rn(x - idx) + 1) * DX);  sx = rn(vx*vx)
//   d2 = rn(sx + sy);  dis = sqrt.rn(d2)
//   t  = trunc( rn( rn(dis * rn(1/1500)) * 12500000.0f ) )
// (XLA algsimp rewrites divide-by-constant -> multiply-by-reciprocal; the two
//  divides become two multiplies; rn(1/rn(8e-8)) == 12500000.0f exactly.)
//   out[b, iy, ix] = (image - min_b) / (max_b - min_b)
// ---------------------------------------------------------------------------

static constexpr float DXc   = 0.001f;
static constexpr float DYc   = 0.001f;
static constexpr float DTF   = (float)(1.0 / 12500000.0);
static constexpr float RCPVS = (float)(1.0 / 1500.0);          // rn(1/1500)
static constexpr float RCPDT = (float)(1.0 / (double)DTF);     // == 12500000.0f

// scratch: un-normalized image sums, (B, Nx*Ny) with p = ix*256 + iy
__device__ float g_scratch[8 * 256 * 256];

// t = trunc( rn( rn(sqrt_rn(d2) * RCPVS) * RCPDT ) )
__device__ __forceinline__ int t_chain(float d2) {
    float dis = __fsqrt_rn(d2);
    float q1  = __fmul_rn(dis, RCPVS);
    float q2  = __fmul_rn(q1, RCPDT);
    return __float2int_rz(q2);
}

// ---------------------------------------------------------------------------
// Kernel 1: per-CTA 64x64 pixel tile, loop over 128 sensors with shared-memory
// time-window staging (double-buffered cp.async).
// ---------------------------------------------------------------------------
#define WCAP4 256                  // window capacity: 256 float4 = 1024 floats

__global__ void __launch_bounds__(256, 1)
das_main(const float* __restrict__ sd, const float* __restrict__ mask)
{
    __shared__ float win[2][WCAP4 * 4];
    __shared__ float dxs[2][64];          // per-ix sx = rn(vx*vx)
    __shared__ float smx[128], smy[128];
    __shared__ int   swb[128], swc[128];

    const int b   = blockIdx.z;
    const int ix0 = blockIdx.x * 64;     // 0-based pixel tile origin
    const int iy0 = blockIdx.y * 64;
    const int tid = threadIdx.x;
    const int iy_off = tid & 63;         // this thread's iy within the tile
    const int ixg    = tid >> 6;         // ix group 0..3 (16 ix each)

    // ---- per-sensor setup: coordinates + staging window bounds -------------
    if (tid < 128) {
        float mxv = mask[((b * 128 + tid) << 1) + 0];
        float myv = mask[((b * 128 + tid) << 1) + 1];
        // separate mul then add (no FMA) — matches HLO mul + add
        float xm = __fadd_rn(__fmul_rn(mxv, 1000.0f), 128.0f);
        float ym = __fadd_rn(__fmul_rn(myv, 1000.0f), 128.0f);
        smx[tid] = xm;
        smy[tid] = ym;

        // corner (1-based) idx values of this tile
        float xl = (float)(ix0 + 1), xh = (float)(ix0 + 64);
        float yl = (float)(iy0 + 1), yh = (float)(iy0 + 64);

        // max distance over tile: at a corner (dis convex in position)
        float ax0 = __fadd_rn(__fsub_rn(xm, xl), 1.0f);
        float ax1 = __fadd_rn(__fsub_rn(xm, xh), 1.0f);
        float ay0 = __fadd_rn(__fsub_rn(ym, yl), 1.0f);
        float ay1 = __fadd_rn(__fsub_rn(ym, yh), 1.0f);
        float vx0 = __fmul_rn(ax0, DXc), vx1 = __fmul_rn(ax1, DXc);
        float vy0 = __fmul_rn(ay0, DYc), vy1 = __fmul_rn(ay1, DYc);
        float sx0 = __fmul_rn(vx0, vx0), sx1 = __fmul_rn(vx1, vx1);
        float sy0 = __fmul_rn(vy0, vy0), sy1 = __fmul_rn(vy1, vy1);
        float sxm = fmaxf(sx0, sx1), sym = fmaxf(sy0, sy1);
        float d2max = __fadd_rn(sxm, sym);

        // min distance over tile: continuous clamp (lower bound), pad covers slop
        float ux = xm + 1.0f, uy = ym + 1.0f;   // sensor position in idx units
        float exd = fmaxf(fmaxf(xl - ux, ux - xh), 0.0f);
        float eyd = fmaxf(fmaxf(yl - uy, uy - yh), 0.0f);
        float vmx = exd * DXc, vmy = eyd * DYc;
        float d2min = vmx * vmx + vmy * vmy;

        int tmin = t_chain(d2min) - 4; if (tmin < 0) tmin = 0;
        int tmax = t_chain(d2max) + 4; if (tmax > 16383) tmax = 16383;

        int wb  = tmin & ~3;                       // 16B-aligned base
        int n4  = ((tmax - wb + 1) + 3) >> 2;      // float4 count
        int mx4 = (16384 - wb) >> 2;
        if (n4 > mx4)   n4 = mx4;
        if (n4 > WCAP4) n4 = WCAP4;
        swb[tid] = wb;
        swc[tid] = (n4 << 2) - 1;                  // clamp max local index
    }
    __syncthreads();

    const float* row_base = sd + (size_t)b * 128 * 16384;

    auto stage = [&](int s, int bi) {
        int wb = swb[s];
        int n4 = (swc[s] + 1) >> 2;
        if (tid < n4) {
            const float* g = row_base + (size_t)s * 16384 + wb + tid * 4;
            uint32_t sa = (uint32_t)__cvta_generic_to_shared(&win[bi][tid * 4]);
            asm volatile("cp.async.cg.shared.global [%0], [%1], 16;\n"
                         :: "r"(sa), "l"(g) : "memory");
        }
        if (tid < 64) {  // per-ix squared x-term sx for this sensor (exact chain)
            float xm  = smx[s];
            float ixf = (float)(ix0 + tid + 1);
            float ax  = __fadd_rn(__fsub_rn(xm, ixf), 1.0f);
            float vx  = __fmul_rn(ax, DXc);
            dxs[bi][tid] = __fmul_rn(vx, vx);
        }
    };

    // prologue: stage sensor 0
    stage(0, 0);
    asm volatile("cp.async.commit_group;\n" ::: "memory");

    const float iyf = (float)(iy0 + iy_off + 1);  // 1-based idy for this thread
    float acc[16];
    #pragma unroll
    for (int k = 0; k < 16; ++k) acc[k] = 0.0f;

    for (int s = 0; s < 128; ++s) {
        const int bi = s & 1;
        asm volatile("cp.async.wait_group 0;\n" ::: "memory");
        __syncthreads();   // window s ready; everyone done reading buffer bi^1

        if (s + 1 < 128) {
            stage(s + 1, bi ^ 1);
            asm volatile("cp.async.commit_group;\n" ::: "memory");
        }

        float ym  = smy[s];
        int   wb  = swb[s];
        int   cmx = swc[s];
        float ay  = __fadd_rn(__fsub_rn(ym, iyf), 1.0f);
        float vy  = __fmul_rn(ay, DYc);
        float sy  = __fmul_rn(vy, vy);    // y-term squared

        const float* wbuf = win[bi];
        const float* dxb  = dxs[bi] + ixg * 16;

        #pragma unroll
        for (int k = 0; k < 16; ++k) {
            float d2 = __fadd_rn(dxb[k], sy);   // rn(sx + sy), no FMA
            int t = t_chain(d2);
            int w = t - wb;
            w = (w < 0) ? 0 : w;
            w = (w > cmx) ? cmx : w;
            acc[k] = __fadd_rn(acc[k], wbuf[w]);
        }
    }

    // write un-normalized sums: scratch[b][(ix)*256 + iy]
    float* osc = g_scratch + b * 65536 + (ix0 + ixg * 16) * 256 + iy0 + iy_off;
    #pragma unroll
    for (int k = 0; k < 16; ++k) osc[k * 256] = acc[k];
}

// ---------------------------------------------------------------------------
// Kernel 2: per-batch min/max + normalize + transpose into output.
// ---------------------------------------------------------------------------
__global__ void __launch_bounds__(256)
das_norm(float* __restrict__ out)
{
    __shared__ float rmn[256], rmx[256];
    const int b   = blockIdx.x;
    const int tid = threadIdx.x;
    const float* img = g_scratch + b * 65536;

    float mn =  3.402823466e38f;
    float mx = -3.402823466e38f;
    for (int i = 0; i < 256; ++i) {
        float v = img[i * 256 + tid];   // coalesced
        mn = fminf(mn, v);
        mx = fmaxf(mx, v);
    }
    rmn[tid] = mn; rmx[tid] = mx;
    __syncthreads();
    for (int o = 128; o > 0; o >>= 1) {
        if (tid < o) {
            rmn[tid] = fminf(rmn[tid], rmn[tid + o]);
            rmx[tid] = fmaxf(rmx[tid], rmx[tid + o]);
        }
        __syncthreads();
    }
    mn = rmn[0]; mx = rmx[0];
    float den = __fsub_rn(mx, mn);

    float* ob = out + b * 65536;
    for (int i = 0; i < 256; ++i) {
        // out[b, iy=i, ix=tid] = norm(image[b, ix=tid, iy=i])
        ob[i * 256 + tid] = __fdiv_rn(__fsub_rn(img[tid * 256 + i], mn), den);
    }
}

// ---------------------------------------------------------------------------
extern "C" void kernel_launch(void* const* d_in, const int* in_sizes, int n_in,
                              void* d_out, int out_size)
{
    const float* sd   = (const float*)d_in[0];   // (8,128,16384) f32
    const float* mask = (const float*)d_in[1];   // (8,128,2) f32
    float* out = (float*)d_out;                  // (8,256,256) f32

    dim3 grid(4, 4, 8);   // 16 tiles of 64x64 per batch, 8 batches = 128 CTAs
    das_main<<<grid, 256>>>(sd, mask);
    das_norm<<<8, 256>>>(out);
}

// round 4
// speedup vs baseline: 1.8118x; 1.8118x over previous
#include <cuda_runtime.h>
#include <cstdint>

// ---------------------------------------------------------------------------
// DAS beamformer — replicates XLA's compiled f32 chain:
//   m  = rn(rn(mask*1000) + 128)                      (separate mul/add, no FMA)
//   vx = rn(rn(rn(x - idx) + 1) * DX);  sx = rn(vx*vx)
//   d2 = rn(sx + sy);  dis = sqrt.rn(d2)
//   t  = trunc( rn( rn(dis * rn(1/1500)) * 12500000.0f ) )
// (XLA algsimp rewrites divide-by-constant -> multiply-by-reciprocal.)
//   out[b, iy, ix] = (image - min_b) / (max_b - min_b)
// ---------------------------------------------------------------------------

static constexpr float DXc   = 0.001f;
static constexpr float DYc   = 0.001f;
static constexpr float DTF   = (float)(1.0 / 12500000.0);
static constexpr float RCPVS = (float)(1.0 / 1500.0);          // rn(1/1500)
static constexpr float RCPDT = (float)(1.0 / (double)DTF);     // == 12500000.0f

// scratch: un-normalized image sums, (B, Nx*Ny) with p = ix*256 + iy
__device__ float g_scratch[8 * 256 * 256];
__device__ float g_pmn[64], g_pmx[64];   // per-(batch, chunk) partial min/max

// t = trunc( rn( rn(sqrt_rn(d2) * RCPVS) * RCPDT ) )
__device__ __forceinline__ int t_chain(float d2) {
    float dis = __fsqrt_rn(d2);
    float q1  = __fmul_rn(dis, RCPVS);
    float q2  = __fmul_rn(q1, RCPDT);
    return __float2int_rz(q2);
}

// ---------------------------------------------------------------------------
// Kernel 1: per-CTA 64x64 pixel tile, 512 threads, loop over 128 sensors with
// 4-deep cp.async window pipeline into shared memory.
// ---------------------------------------------------------------------------
#define WCAP4 256                  // window capacity: 256 float4 = 1024 floats
#define NSTG  4                    // pipeline depth (buffers)

__global__ void __launch_bounds__(512, 1)
das_main(const float* __restrict__ sd, const float* __restrict__ mask)
{
    __shared__ float win[NSTG][WCAP4 * 4];
    __shared__ __align__(16) float dxs[NSTG][64];   // per-ix sx = rn(vx*vx)
    __shared__ float smx[128], smy[128];
    __shared__ int   swb[128], swc[128];

    const int b   = blockIdx.z;
    const int ix0 = blockIdx.x * 64;     // 0-based pixel tile origin
    const int iy0 = blockIdx.y * 64;
    const int tid = threadIdx.x;
    const int iy_off = tid & 63;         // this thread's iy within the tile
    const int ixg    = tid >> 6;         // ix group 0..7 (8 ix each)

    // ---- per-sensor setup: coordinates + staging window bounds -------------
    if (tid < 128) {
        float mxv = mask[((b * 128 + tid) << 1) + 0];
        float myv = mask[((b * 128 + tid) << 1) + 1];
        // separate mul then add (no FMA) — matches HLO mul + add
        float xm = __fadd_rn(__fmul_rn(mxv, 1000.0f), 128.0f);
        float ym = __fadd_rn(__fmul_rn(myv, 1000.0f), 128.0f);
        smx[tid] = xm;
        smy[tid] = ym;

        // corner (1-based) idx values of this tile
        float xl = (float)(ix0 + 1), xh = (float)(ix0 + 64);
        float yl = (float)(iy0 + 1), yh = (float)(iy0 + 64);

        // max distance over tile: at a corner (monotone exact chain per corner)
        float ax0 = __fadd_rn(__fsub_rn(xm, xl), 1.0f);
        float ax1 = __fadd_rn(__fsub_rn(xm, xh), 1.0f);
        float ay0 = __fadd_rn(__fsub_rn(ym, yl), 1.0f);
        float ay1 = __fadd_rn(__fsub_rn(ym, yh), 1.0f);
        float vx0 = __fmul_rn(ax0, DXc), vx1 = __fmul_rn(ax1, DXc);
        float vy0 = __fmul_rn(ay0, DYc), vy1 = __fmul_rn(ay1, DYc);
        float sx0 = __fmul_rn(vx0, vx0), sx1 = __fmul_rn(vx1, vx1);
        float sy0 = __fmul_rn(vy0, vy0), sy1 = __fmul_rn(vy1, vy1);
        float sxm = fmaxf(sx0, sx1), sym = fmaxf(sy0, sy1);
        float d2max = __fadd_rn(sxm, sym);

        // min distance over tile: continuous clamp (lower bound), pad covers slop
        float ux = xm + 1.0f, uy = ym + 1.0f;   // sensor position in idx units
        float exd = fmaxf(fmaxf(xl - ux, ux - xh), 0.0f);
        float eyd = fmaxf(fmaxf(yl - uy, uy - yh), 0.0f);
        float vmx = exd * DXc, vmy = eyd * DYc;
        float d2min = vmx * vmx + vmy * vmy;

        int tmin = t_chain(d2min) - 4; if (tmin < 0) tmin = 0;
        int tmax = t_chain(d2max) + 4; if (tmax > 16383) tmax = 16383;

        int wb  = tmin & ~3;                       // 16B-aligned base
        int n4  = ((tmax - wb + 1) + 3) >> 2;      // float4 count
        int mx4 = (16384 - wb) >> 2;
        if (n4 > mx4)   n4 = mx4;
        if (n4 > WCAP4) n4 = WCAP4;
        swb[tid] = wb;
        swc[tid] = (n4 << 2) - 1;                  // clamp max local index
    }
    __syncthreads();

    const float* row_base = sd + (size_t)b * 128 * 16384;

    auto stage = [&](int s) {
        const int bi = s & (NSTG - 1);
        int wb = swb[s];
        int n4 = (swc[s] + 1) >> 2;
        if (tid < n4) {
            const float* g = row_base + (size_t)s * 16384 + wb + tid * 4;
            uint32_t sa = (uint32_t)__cvta_generic_to_shared(&win[bi][tid * 4]);
            asm volatile("cp.async.cg.shared.global [%0], [%1], 16;\n"
                         :: "r"(sa), "l"(g) : "memory");
        }
        if (tid < 64) {  // per-ix squared x-term sx for this sensor (exact chain)
            float xm  = smx[s];
            float ixf = (float)(ix0 + tid + 1);
            float ax  = __fadd_rn(__fsub_rn(xm, ixf), 1.0f);
            float vx  = __fmul_rn(ax, DXc);
            dxs[bi][tid] = __fmul_rn(vx, vx);
        }
    };

    // prologue: stage sensors 0..2, one commit group each
    stage(0); asm volatile("cp.async.commit_group;\n" ::: "memory");
    stage(1); asm volatile("cp.async.commit_group;\n" ::: "memory");
    stage(2); asm volatile("cp.async.commit_group;\n" ::: "memory");

    const float iyf = (float)(iy0 + iy_off + 1);  // 1-based idy for this thread
    float acc[8];
    #pragma unroll
    for (int k = 0; k < 8; ++k) acc[k] = 0.0f;

    for (int s = 0; s < 128; ++s) {
        const int bi = s & (NSTG - 1);
        // 3 groups in flight at entry (some possibly empty near tail):
        // waiting for <=2 pending guarantees stage s is complete.
        asm volatile("cp.async.wait_group 2;\n" ::: "memory");
        __syncthreads();   // window s ready; everyone done reading buffer bi+1 (mod 4)

        if (s + 3 < 128) stage(s + 3);
        asm volatile("cp.async.commit_group;\n" ::: "memory");  // keep group count invariant

        float ym  = smy[s];
        int   wb  = swb[s];
        int   cmx = swc[s];
        float ay  = __fadd_rn(__fsub_rn(ym, iyf), 1.0f);
        float vy  = __fmul_rn(ay, DYc);
        float sy  = __fmul_rn(vy, vy);    // y-term squared

        const float* wbuf = win[bi];
        const float4* dxb4 = reinterpret_cast<const float4*>(dxs[bi] + ixg * 8);
        float4 sx0 = dxb4[0];
        float4 sx1 = dxb4[1];
        float sx[8] = { sx0.x, sx0.y, sx0.z, sx0.w, sx1.x, sx1.y, sx1.z, sx1.w };

        #pragma unroll
        for (int k = 0; k < 8; ++k) {
            float d2 = __fadd_rn(sx[k], sy);   // rn(sx + sy), no FMA
            int t = t_chain(d2);
            int w = t - wb;
            w = (w < 0) ? 0 : w;
            w = (w > cmx) ? cmx : w;
            acc[k] = __fadd_rn(acc[k], wbuf[w]);
        }
    }

    // write un-normalized sums: scratch[b][(ix)*256 + iy]
    float* osc = g_scratch + b * 65536 + (ix0 + ixg * 8) * 256 + iy0 + iy_off;
    #pragma unroll
    for (int k = 0; k < 8; ++k) osc[k * 256] = acc[k];
}

// ---------------------------------------------------------------------------
// Kernel 2: per-(batch, chunk) partial min/max, fully coalesced.
// grid = 64 (8 batches x 8 chunks of 8192), 256 threads.
// ---------------------------------------------------------------------------
__global__ void __launch_bounds__(256)
das_minmax()
{
    __shared__ float rmn[256], rmx[256];
    const int b     = blockIdx.x >> 3;
    const int chunk = blockIdx.x & 7;
    const int tid   = threadIdx.x;
    const float* base = g_scratch + b * 65536 + chunk * 8192;

    float mn =  3.402823466e38f;
    float mx = -3.402823466e38f;
    #pragma unroll 4
    for (int i = tid; i < 8192; i += 256) {
        float v = base[i];
        mn = fminf(mn, v);
        mx = fmaxf(mx, v);
    }
    rmn[tid] = mn; rmx[tid] = mx;
    __syncthreads();
    for (int o = 128; o > 0; o >>= 1) {
        if (tid < o) {
            rmn[tid] = fminf(rmn[tid], rmn[tid + o]);
            rmx[tid] = fmaxf(rmx[tid], rmx[tid + o]);
        }
        __syncthreads();
    }
    if (tid == 0) { g_pmn[blockIdx.x] = rmn[0]; g_pmx[blockIdx.x] = rmx[0]; }
}

// ---------------------------------------------------------------------------
// Kernel 3: normalize + transpose via 32x32 smem tiles, coalesced both ways.
// grid = (64, 8): 64 tiles per batch. block 256 = 32x8.
// ---------------------------------------------------------------------------
__global__ void __launch_bounds__(256)
das_norm_t(float* __restrict__ out)
{
    __shared__ float tile[32][33];
    const int b  = blockIdx.y;
    const int tx = blockIdx.x & 7;   // ix tile
    const int ty = blockIdx.x >> 3;  // iy tile
    const int lx = threadIdx.x & 31;
    const int lr = threadIdx.x >> 5; // 0..7

    // reduce the 8 per-batch partials (redundant per CTA, trivial)
    float mn = g_pmn[b * 8 + 0], mx = g_pmx[b * 8 + 0];
    #pragma unroll
    for (int c = 1; c < 8; ++c) {
        mn = fminf(mn, g_pmn[b * 8 + c]);
        mx = fmaxf(mx, g_pmx[b * 8 + c]);
    }
    float den = __fsub_rn(mx, mn);

    const float* img = g_scratch + b * 65536;
    // load: rows are ix (tx*32 + r), cols iy (ty*32 + lx) — coalesced
    #pragma unroll
    for (int r = lr; r < 32; r += 8) {
        tile[r][lx] = img[(tx * 32 + r) * 256 + ty * 32 + lx];
    }
    __syncthreads();

    float* ob = out + b * 65536;
    // store: out[b, iy, ix] — rows iy (ty*32 + r), cols ix (tx*32 + lx) — coalesced
    #pragma unroll
    for (int r = lr; r < 32; r += 8) {
        float v = tile[lx][r];
        ob[(ty * 32 + r) * 256 + tx * 32 + lx] = __fdiv_rn(__fsub_rn(v, mn), den);
    }
}

// ---------------------------------------------------------------------------
extern "C" void kernel_launch(void* const* d_in, const int* in_sizes, int n_in,
                              void* d_out, int out_size)
{
    const float* sd   = (const float*)d_in[0];   // (8,128,16384) f32
    const float* mask = (const float*)d_in[1];   // (8,128,2) f32
    float* out = (float*)d_out;                  // (8,256,256) f32

    dim3 grid(4, 4, 8);   // 16 tiles of 64x64 per batch, 8 batches = 128 CTAs
    das_main<<<grid, 512>>>(sd, mask);
    das_minmax<<<64, 256>>>();
    das_norm_t<<<dim3(64, 8), 256>>>(out);
}

// round 6
// speedup vs baseline: 2.0924x; 1.1549x over previous
#include <cuda_runtime.h>
#include <cstdint>

// ---------------------------------------------------------------------------
// DAS beamformer — replicates XLA's compiled f32 chain:
//   m  = rn(rn(mask*1000) + 128)                      (separate mul/add, no FMA)
//   vx = rn(rn(rn(x - idx) + 1) * DX);  sx = rn(vx*vx)
//   d2 = rn(sx + sy);  dis = sqrt.rn(d2)
//   t  = trunc( rn( rn(dis * rn(1/1500)) * 12500000.0f ) )
// (XLA algsimp rewrites divide-by-constant -> multiply-by-reciprocal.)
//   out[b, iy, ix] = (image - min_b) / (max_b - min_b)
// ---------------------------------------------------------------------------

static constexpr float DXc   = 0.001f;
static constexpr float DYc   = 0.001f;
static constexpr float DTF   = (float)(1.0 / 12500000.0);
static constexpr float RCPVS = (float)(1.0 / 1500.0);          // rn(1/1500)
static constexpr float RCPDT = (float)(1.0 / (double)DTF);     // == 12500000.0f

// scratch: un-normalized image sums, (B, Nx*Ny) with p = ix*256 + iy
__device__ float g_scratch[8 * 256 * 256];
__device__ float g_pmn[64], g_pmx[64];   // per-(batch, chunk) partial min/max

// t = trunc( rn( rn(sqrt_rn(d2) * RCPVS) * RCPDT ) )
__device__ __forceinline__ int t_chain(float d2) {
    float dis = __fsqrt_rn(d2);
    float q1  = __fmul_rn(dis, RCPVS);
    float q2  = __fmul_rn(q1, RCPDT);
    return __float2int_rz(q2);
}

// ---------------------------------------------------------------------------
// Kernel 1: per-CTA 32x32 pixel tile, 256 threads, loop over 128 sensors with
// 4-deep cp.async window pipeline into shared memory.
// Window range for a 32x32 tile <= 31*sqrt(2)*DX/VS/DT + pads = ~382 < 512,
// so with +/-8 sample padding the staged window provably covers every gather:
// no per-gather clamping needed.
// ---------------------------------------------------------------------------
#define WCAP4 128                  // window capacity: 128 float4 = 512 floats
#define NSTG  4                    // pipeline depth (buffers)

__global__ void __launch_bounds__(256)
das_main(const float* __restrict__ sd, const float* __restrict__ mask)
{
    __shared__ float win[NSTG][WCAP4 * 4];
    __shared__ __align__(16) float dxs[NSTG][32];   // per-ix sx = rn(vx*vx)
    __shared__ float smx[128], smy[128];
    __shared__ int   swb[128], swn[128];

    const int b   = blockIdx.z;
    const int ix0 = blockIdx.x * 32;     // 0-based pixel tile origin
    const int iy0 = blockIdx.y * 32;
    const int tid = threadIdx.x;
    const int iy_off = tid & 31;         // this thread's iy within the tile
    const int ixg    = tid >> 5;         // ix group 0..7 (4 ix each)

    // ---- per-sensor setup: coordinates + staging window bounds -------------
    if (tid < 128) {
        float mxv = mask[((b * 128 + tid) << 1) + 0];
        float myv = mask[((b * 128 + tid) << 1) + 1];
        // separate mul then add (no FMA) — matches HLO mul + add
        float xm = __fadd_rn(__fmul_rn(mxv, 1000.0f), 128.0f);
        float ym = __fadd_rn(__fmul_rn(myv, 1000.0f), 128.0f);
        smx[tid] = xm;
        smy[tid] = ym;

        // corner (1-based) idx values of this tile
        float xl = (float)(ix0 + 1), xh = (float)(ix0 + 32);
        float yl = (float)(iy0 + 1), yh = (float)(iy0 + 32);

        // max distance over tile: at a corner (monotone exact chain per corner)
        float ax0 = __fadd_rn(__fsub_rn(xm, xl), 1.0f);
        float ax1 = __fadd_rn(__fsub_rn(xm, xh), 1.0f);
        float ay0 = __fadd_rn(__fsub_rn(ym, yl), 1.0f);
        float ay1 = __fadd_rn(__fsub_rn(ym, yh), 1.0f);
        float vx0 = __fmul_rn(ax0, DXc), vx1 = __fmul_rn(ax1, DXc);
        float vy0 = __fmul_rn(ay0, DYc), vy1 = __fmul_rn(ay1, DYc);
        float sx0 = __fmul_rn(vx0, vx0), sx1 = __fmul_rn(vx1, vx1);
        float sy0 = __fmul_rn(vy0, vy0), sy1 = __fmul_rn(vy1, vy1);
        float sxm = fmaxf(sx0, sx1), sym = fmaxf(sy0, sy1);
        float d2max = __fadd_rn(sxm, sym);

        // min distance over tile: continuous clamp (lower bound), pad covers slop
        float ux = xm + 1.0f, uy = ym + 1.0f;   // sensor position in idx units
        float exd = fmaxf(fmaxf(xl - ux, ux - xh), 0.0f);
        float eyd = fmaxf(fmaxf(yl - uy, uy - yh), 0.0f);
        float vmx = exd * DXc, vmy = eyd * DYc;
        float d2min = vmx * vmx + vmy * vmy;

        int tmin = t_chain(d2min) - 8; if (tmin < 0) tmin = 0;
        int tmax = t_chain(d2max) + 8; if (tmax > 16383) tmax = 16383;

        int wb  = tmin & ~3;                       // 16B-aligned base
        int n4  = ((tmax - wb + 1) + 3) >> 2;      // float4 count
        int mx4 = (16384 - wb) >> 2;
        if (n4 > mx4)   n4 = mx4;
        if (n4 > WCAP4) n4 = WCAP4;                // provably never binds (<=100)
        swb[tid] = wb;
        swn[tid] = n4;
    }
    __syncthreads();

    const float* row_base = sd + (size_t)b * 128 * 16384;

    auto stage = [&](int s) {
        const int bi = s & (NSTG - 1);
        int wb = swb[s];
        if (tid < swn[s]) {
            const float* g = row_base + (size_t)s * 16384 + wb + tid * 4;
            uint32_t sa = (uint32_t)__cvta_generic_to_shared(&win[bi][tid * 4]);
            asm volatile("cp.async.cg.shared.global [%0], [%1], 16;\n"
                         :: "r"(sa), "l"(g) : "memory");
        }
        if (tid >= 128 && tid < 160) {   // warp 4: per-ix sx (exact chain)
            int l = tid - 128;
            float xm  = smx[s];
            float ixf = (float)(ix0 + l + 1);
            float ax  = __fadd_rn(__fsub_rn(xm, ixf), 1.0f);
            float vx  = __fmul_rn(ax, DXc);
            dxs[bi][l] = __fmul_rn(vx, vx);
        }
    };

    // prologue: stage sensors 0..2, one commit group each
    stage(0); asm volatile("cp.async.commit_group;\n" ::: "memory");
    stage(1); asm volatile("cp.async.commit_group;\n" ::: "memory");
    stage(2); asm volatile("cp.async.commit_group;\n" ::: "memory");

    const float iyf = (float)(iy0 + iy_off + 1);  // 1-based idy for this thread
    float acc0 = 0.0f, acc1 = 0.0f, acc2 = 0.0f, acc3 = 0.0f;

    for (int s = 0; s < 128; ++s) {
        const int bi = s & (NSTG - 1);
        // 3 groups in flight at entry (some possibly empty near tail):
        // waiting for <=2 pending guarantees stage s is complete.
        asm volatile("cp.async.wait_group 2;\n" ::: "memory");
        __syncthreads();   // window s ready; everyone done reading buffer bi+1 (mod 4)

        if (s + 3 < 128) stage(s + 3);
        asm volatile("cp.async.commit_group;\n" ::: "memory");  // keep group count invariant

        float ym  = smy[s];
        int   wb  = swb[s];
        float ay  = __fadd_rn(__fsub_rn(ym, iyf), 1.0f);
        float vy  = __fmul_rn(ay, DYc);
        float sy  = __fmul_rn(vy, vy);    // y-term squared

        const float* wbuf = win[bi];
        float4 sx4 = *reinterpret_cast<const float4*>(dxs[bi] + ixg * 4);

        // rn(sx + sy), no FMA; window provably covers t: no clamps
        int t0 = t_chain(__fadd_rn(sx4.x, sy));
        int t1 = t_chain(__fadd_rn(sx4.y, sy));
        int t2 = t_chain(__fadd_rn(sx4.z, sy));
        int t3 = t_chain(__fadd_rn(sx4.w, sy));
        acc0 = __fadd_rn(acc0, wbuf[t0 - wb]);
        acc1 = __fadd_rn(acc1, wbuf[t1 - wb]);
        acc2 = __fadd_rn(acc2, wbuf[t2 - wb]);
        acc3 = __fadd_rn(acc3, wbuf[t3 - wb]);
    }

    // write un-normalized sums: scratch[b][(ix)*256 + iy]
    float* osc = g_scratch + b * 65536 + (ix0 + ixg * 4) * 256 + iy0 + iy_off;
    osc[0]   = acc0;
    osc[256] = acc1;
    osc[512] = acc2;
    osc[768] = acc3;
}

// ---------------------------------------------------------------------------
// Kernel 2: per-(batch, chunk) partial min/max, fully coalesced.
// grid = 64 (8 batches x 8 chunks of 8192), 256 threads.
// ---------------------------------------------------------------------------
__global__ void __launch_bounds__(256)
das_minmax()
{
    __shared__ float rmn[256], rmx[256];
    const int b     = blockIdx.x >> 3;
    const int chunk = blockIdx.x & 7;
    const int tid   = threadIdx.x;
    const float* base = g_scratch + b * 65536 + chunk * 8192;

    float mn =  3.402823466e38f;
    float mx = -3.402823466e38f;
    #pragma unroll 4
    for (int i = tid; i < 8192; i += 256) {
        float v = base[i];
        mn = fminf(mn, v);
        mx = fmaxf(mx, v);
    }
    rmn[tid] = mn; rmx[tid] = mx;
    __syncthreads();
    for (int o = 128; o > 0; o >>= 1) {
        if (tid < o) {
            rmn[tid] = fminf(rmn[tid], rmn[tid + o]);
            rmx[tid] = fmaxf(rmx[tid], rmx[tid + o]);
        }
        __syncthreads();
    }
    if (tid == 0) { g_pmn[blockIdx.x] = rmn[0]; g_pmx[blockIdx.x] = rmx[0]; }
}

// ---------------------------------------------------------------------------
// Kernel 3: normalize + transpose via 32x32 smem tiles, coalesced both ways.
// grid = (64, 8): 64 tiles per batch. block 256 = 32x8.
// ---------------------------------------------------------------------------
__global__ void __launch_bounds__(256)
das_norm_t(float* __restrict__ out)
{
    __shared__ float tile[32][33];
    const int b  = blockIdx.y;
    const int tx = blockIdx.x & 7;   // ix tile
    const int ty = blockIdx.x >> 3;  // iy tile
    const int lx = threadIdx.x & 31;
    const int lr = threadIdx.x >> 5; // 0..7

    // reduce the 8 per-batch partials (redundant per CTA, trivial)
    float mn = g_pmn[b * 8 + 0], mx = g_pmx[b * 8 + 0];
    #pragma unroll
    for (int c = 1; c < 8; ++c) {
        mn = fminf(mn, g_pmn[b * 8 + c]);
        mx = fmaxf(mx, g_pmx[b * 8 + c]);
    }
    float den = __fsub_rn(mx, mn);

    const float* img = g_scratch + b * 65536;
    // load: rows are ix (tx*32 + r), cols iy (ty*32 + lx) — coalesced
    #pragma unroll
    for (int r = lr; r < 32; r += 8) {
        tile[r][lx] = img[(tx * 32 + r) * 256 + ty * 32 + lx];
    }
    __syncthreads();

    float* ob = out + b * 65536;
    // store: out[b, iy, ix] — rows iy (ty*32 + r), cols ix (tx*32 + lx) — coalesced
    #pragma unroll
    for (int r = lr; r < 32; r += 8) {
        float v = tile[lx][r];
        ob[(ty * 32 + r) * 256 + tx * 32 + lx] = __fdiv_rn(__fsub_rn(v, mn), den);
    }
}

// ---------------------------------------------------------------------------
extern "C" void kernel_launch(void* const* d_in, const int* in_sizes, int n_in,
                              void* d_out, int out_size)
{
    const float* sd   = (const float*)d_in[0];   // (8,128,16384) f32
    const float* mask = (const float*)d_in[1];   // (8,128,2) f32
    float* out = (float*)d_out;                  // (8,256,256) f32

    dim3 grid(8, 8, 8);   // 64 tiles of 32x32 per batch, 8 batches = 512 CTAs
    das_main<<<grid, 256>>>(sd, mask);
    das_minmax<<<64, 256>>>();
    das_norm_t<<<dim3(64, 8), 256>>>(out);
}

// round 8
// speedup vs baseline: 2.7949x; 1.3358x over previous
#include <cuda_runtime.h>
#include <cstdint>

// ---------------------------------------------------------------------------
// DAS beamformer — replicates XLA's compiled f32 chain:
//   m  = rn(rn(mask*1000) + 128)                      (separate mul/add, no FMA)
//   vx = rn(rn(rn(x - idx) + 1) * DX);  sx = rn(vx*vx)
//   d2 = rn(sx + sy);  dis = sqrt.rn(d2)
//   t  = trunc( rn( rn(dis * rn(1/1500)) * 12500000.0f ) )
// (XLA algsimp rewrites divide-by-constant -> multiply-by-reciprocal.)
//   out[b, iy, ix] = (image - min_b) / (max_b - min_b)
// ---------------------------------------------------------------------------

static constexpr float DXc   = 0.001f;
static constexpr float DYc   = 0.001f;
static constexpr float DTF   = (float)(1.0 / 12500000.0);
static constexpr float RCPVS = (float)(1.0 / 1500.0);          // rn(1/1500)
static constexpr float RCPDT = (float)(1.0 / (double)DTF);     // == 12500000.0f

// scratch: two sensor-half planes of un-normalized sums.
// plane (h*8 + b), pixel p = ix*256 + iy. Final image = plane0 + plane1.
__device__ float g_scratch[16 * 65536];
__device__ float g_pmn[64], g_pmx[64];   // per-(batch, chunk) partial min/max

// t = trunc( rn( rn(sqrt_rn(d2) * RCPVS) * RCPDT ) )
__device__ __forceinline__ int t_chain(float d2) {
    float dis = __fsqrt_rn(d2);
    float q1  = __fmul_rn(dis, RCPVS);
    float q2  = __fmul_rn(q1, RCPDT);
    return __float2int_rz(q2);
}

// ---------------------------------------------------------------------------
// Kernel 1: per-CTA 32x32 pixel tile x 64-sensor half, 256 threads.
// 4-deep cp.async window pipeline; sx/sy term tables precomputed in smem.
// Window range for a 32x32 tile <= 31*sqrt(2)*DX/VS/DT + pads < 512 floats,
// so with +/-8 sample padding the staged window provably covers every gather.
// ---------------------------------------------------------------------------
#define WCAP4 128                  // window capacity: 128 float4 = 512 floats
#define NSTG  4                    // pipeline depth (buffers)
#define NSEN  64                   // sensors per CTA (half of 128)

__global__ void __launch_bounds__(256)
das_main(const float* __restrict__ sd, const float* __restrict__ mask)
{
    __shared__ float win[NSTG][WCAP4 * 4];
    __shared__ __align__(16) float sxt[NSEN * 32];   // sx = rn(vx*vx) per (s, ix)
    __shared__ float syt[NSEN * 32];                 // sy = rn(vy*vy) per (s, iy)
    __shared__ float smx[NSEN], smy[NSEN];
    __shared__ int   swb[NSEN], swn[NSEN];

    const int zb  = blockIdx.z;
    const int b   = zb >> 1;             // batch
    const int s_base = (zb & 1) << 6;    // sensor half: 0 or 64
    const int ix0 = blockIdx.x * 32;     // 0-based pixel tile origin
    const int iy0 = blockIdx.y * 32;
    const int tid = threadIdx.x;
    const int iy_off = tid & 31;         // this thread's iy within the tile
    const int ixg    = tid >> 5;         // ix group 0..7 (4 ix each)

    // ---- phase A: per-sensor coordinates + staging window bounds -----------
    if (tid < NSEN) {
        int sg = s_base + tid;
        float mxv = mask[((b * 128 + sg) << 1) + 0];
        float myv = mask[((b * 128 + sg) << 1) + 1];
        // separate mul then add (no FMA) — matches HLO mul + add
        float xm = __fadd_rn(__fmul_rn(mxv, 1000.0f), 128.0f);
        float ym = __fadd_rn(__fmul_rn(myv, 1000.0f), 128.0f);
        smx[tid] = xm;
        smy[tid] = ym;

        // corner (1-based) idx values of this tile
        float xl = (float)(ix0 + 1), xh = (float)(ix0 + 32);
        float yl = (float)(iy0 + 1), yh = (float)(iy0 + 32);

        // max distance over tile: at a corner (monotone exact chain per corner)
        float ax0 = __fadd_rn(__fsub_rn(xm, xl), 1.0f);
        float ax1 = __fadd_rn(__fsub_rn(xm, xh), 1.0f);
        float ay0 = __fadd_rn(__fsub_rn(ym, yl), 1.0f);
        float ay1 = __fadd_rn(__fsub_rn(ym, yh), 1.0f);
        float vx0 = __fmul_rn(ax0, DXc), vx1 = __fmul_rn(ax1, DXc);
        float vy0 = __fmul_rn(ay0, DYc), vy1 = __fmul_rn(ay1, DYc);
        float sx0 = __fmul_rn(vx0, vx0), sx1 = __fmul_rn(vx1, vx1);
        float sy0 = __fmul_rn(vy0, vy0), sy1 = __fmul_rn(vy1, vy1);
        float d2max = __fadd_rn(fmaxf(sx0, sx1), fmaxf(sy0, sy1));

        // min distance over tile: continuous clamp (lower bound), pad covers slop
        float ux = xm + 1.0f, uy = ym + 1.0f;   // sensor position in idx units
        float exd = fmaxf(fmaxf(xl - ux, ux - xh), 0.0f);
        float eyd = fmaxf(fmaxf(yl - uy, uy - yh), 0.0f);
        float vmx = exd * DXc, vmy = eyd * DYc;
        float d2min = vmx * vmx + vmy * vmy;

        int tmin = t_chain(d2min) - 8; if (tmin < 0) tmin = 0;
        int tmax = t_chain(d2max) + 8; if (tmax > 16383) tmax = 16383;

        int wb  = tmin & ~3;                       // 16B-aligned base
        int n4  = ((tmax - wb + 1) + 3) >> 2;      // float4 count
        int mx4 = (16384 - wb) >> 2;
        if (n4 > mx4)   n4 = mx4;
        if (n4 > WCAP4) n4 = WCAP4;                // provably never binds (<=100)
        swb[tid] = wb;
        swn[tid] = n4;
    }
    __syncthreads();

    // ---- phase B: precompute sx / sy term tables (exact chains) ------------
    #pragma unroll
    for (int i = tid; i < NSEN * 32; i += 256) {
        int s = i >> 5, l = i & 31;
        float xm  = smx[s], ym = smy[s];
        float ixf = (float)(ix0 + l + 1);
        float iyf = (float)(iy0 + l + 1);
        float ax  = __fadd_rn(__fsub_rn(xm, ixf), 1.0f);
        float vx  = __fmul_rn(ax, DXc);
        sxt[i] = __fmul_rn(vx, vx);
        float ay  = __fadd_rn(__fsub_rn(ym, iyf), 1.0f);
        float vy  = __fmul_rn(ay, DYc);
        syt[i] = __fmul_rn(vy, vy);
    }
    __syncthreads();

    const float* row_base = sd + (size_t)b * 128 * 16384 + (size_t)s_base * 16384;

    auto stage = [&](int s) {   // caller guarantees tid < 128 (warps 0..3)
        const int bi = s & (NSTG - 1);
        int wb = swb[s];
        if (tid < swn[s]) {
            const float* g = row_base + (size_t)s * 16384 + wb + tid * 4;
            uint32_t sa = (uint32_t)__cvta_generic_to_shared(&win[bi][tid * 4]);
            asm volatile("cp.async.cg.shared.global [%0], [%1], 16;\n"
                         :: "r"(sa), "l"(g) : "memory");
        }
    };

    // prologue: stage sensors 0..2, one commit group each
    if (tid < 128) { stage(0); }
    asm volatile("cp.async.commit_group;\n" ::: "memory");
    if (tid < 128) { stage(1); }
    asm volatile("cp.async.commit_group;\n" ::: "memory");
    if (tid < 128) { stage(2); }
    asm volatile("cp.async.commit_group;\n" ::: "memory");

    float acc0 = 0.0f, acc1 = 0.0f, acc2 = 0.0f, acc3 = 0.0f;

    for (int s = 0; s < NSEN; ++s) {
        const int bi = s & (NSTG - 1);
        // 3 groups in flight at entry (some possibly empty near tail):
        // waiting for <=2 pending guarantees stage s is complete.
        asm volatile("cp.async.wait_group 2;\n" ::: "memory");
        __syncthreads();   // window s ready; everyone done reading buffer bi+1 (mod 4)

        if (tid < 128) { if (s + 3 < NSEN) stage(s + 3); }
        asm volatile("cp.async.commit_group;\n" ::: "memory");  // keep count invariant

        const float* wofs = &win[bi][0] - swb[s];     // pre-offset gather base
        float sy = syt[(s << 5) + iy_off];            // stride-1 LDS, no conflicts
        float4 sx4 = *reinterpret_cast<const float4*>(sxt + (s << 5) + (ixg << 2)); // broadcast

        // rn(sx + sy), no FMA; window provably covers t: no clamps
        int t0 = t_chain(__fadd_rn(sx4.x, sy));
        int t1 = t_chain(__fadd_rn(sx4.y, sy));
        int t2 = t_chain(__fadd_rn(sx4.z, sy));
        int t3 = t_chain(__fadd_rn(sx4.w, sy));
        acc0 = __fadd_rn(acc0, wofs[t0]);
        acc1 = __fadd_rn(acc1, wofs[t1]);
        acc2 = __fadd_rn(acc2, wofs[t2]);
        acc3 = __fadd_rn(acc3, wofs[t3]);
    }

    // write un-normalized partial sums: plane (half*8 + b)
    float* osc = g_scratch + ((zb & 1) * 8 + b) * 65536
               + (ix0 + ixg * 4) * 256 + iy0 + iy_off;
    osc[0]   = acc0;
    osc[256] = acc1;
    osc[512] = acc2;
    osc[768] = acc3;
}

// ---------------------------------------------------------------------------
// Kernel 2: per-(batch, chunk) partial min/max over plane0+plane1, coalesced.
// grid = 64 (8 batches x 8 chunks of 8192), 256 threads.
// ---------------------------------------------------------------------------
__global__ void __launch_bounds__(256)
das_minmax()
{
    __shared__ float rmn[256], rmx[256];
    const int b     = blockIdx.x >> 3;
    const int chunk = blockIdx.x & 7;
    const int tid   = threadIdx.x;
    const float* p0 = g_scratch + b * 65536 + chunk * 8192;
    const float* p1 = p0 + 8 * 65536;

    float mn =  3.402823466e38f;
    float mx = -3.402823466e38f;
    #pragma unroll 4
    for (int i = tid; i < 8192; i += 256) {
        float v = __fadd_rn(p0[i], p1[i]);
        mn = fminf(mn, v);
        mx = fmaxf(mx, v);
    }
    rmn[tid] = mn; rmx[tid] = mx;
    __syncthreads();
    for (int o = 128; o > 0; o >>= 1) {
        if (tid < o) {
            rmn[tid] = fminf(rmn[tid], rmn[tid + o]);
            rmx[tid] = fmaxf(rmx[tid], rmx[tid + o]);
        }
        __syncthreads();
    }
    if (tid == 0) { g_pmn[blockIdx.x] = rmn[0]; g_pmx[blockIdx.x] = rmx[0]; }
}

// ---------------------------------------------------------------------------
// Kernel 3: normalize + transpose via 32x32 smem tiles, coalesced both ways.
// grid = (64, 8): 64 tiles per batch. block 256 = 32x8.
// ---------------------------------------------------------------------------
__global__ void __launch_bounds__(256)
das_norm_t(float* __restrict__ out)
{
    __shared__ float tile[32][33];
    const int b  = blockIdx.y;
    const int tx = blockIdx.x & 7;   // ix tile
    const int ty = blockIdx.x >> 3;  // iy tile
    const int lx = threadIdx.x & 31;
    const int lr = threadIdx.x >> 5; // 0..7

    // reduce the 8 per-batch partials (redundant per CTA, trivial)
    float mn = g_pmn[b * 8 + 0], mx = g_pmx[b * 8 + 0];
    #pragma unroll
    for (int c = 1; c < 8; ++c) {
        mn = fminf(mn, g_pmn[b * 8 + c]);
        mx = fmaxf(mx, g_pmx[b * 8 + c]);
    }
    float den = __fsub_rn(mx, mn);

    const float* i0 = g_scratch + b * 65536;
    const float* i1 = i0 + 8 * 65536;
    // load: rows are ix (tx*32 + r), cols iy (ty*32 + lx) — coalesced
    #pragma unroll
    for (int r = lr; r < 32; r += 8) {
        int p = (tx * 32 + r) * 256 + ty * 32 + lx;
        tile[r][lx] = __fadd_rn(i0[p], i1[p]);   // same order as das_minmax
    }
    __syncthreads();

    float* ob = out + b * 65536;
    // store: out[b, iy, ix] — rows iy (ty*32 + r), cols ix (tx*32 + lx) — coalesced
    #pragma unroll
    for (int r = lr; r < 32; r += 8) {
        float v = tile[lx][r];
        ob[(ty * 32 + r) * 256 + tx * 32 + lx] = __fdiv_rn(__fsub_rn(v, mn), den);
    }
}

// ---------------------------------------------------------------------------
extern "C" void kernel_launch(void* const* d_in, const int* in_sizes, int n_in,
                              void* d_out, int out_size)
{
    const float* sd   = (const float*)d_in[0];   // (8,128,16384) f32
    const float* mask = (const float*)d_in[1];   // (8,128,2) f32
    float* out = (float*)d_out;                  // (8,256,256) f32

    // z = batch*2 + sensor-half: 1024 CTAs -> ~7/SM, single co-resident wave
    dim3 grid(8, 8, 16);
    das_main<<<grid, 256>>>(sd, mask);
    das_minmax<<<64, 256>>>();
    das_norm_t<<<dim3(64, 8), 256>>>(out);
}

// round 10
// speedup vs baseline: 2.9043x; 1.0391x over previous
#include <cuda_runtime.h>
#include <cstdint>

// ---------------------------------------------------------------------------
// DAS beamformer — replicates XLA's compiled f32 chain:
//   m  = rn(rn(mask*1000) + 128)                      (separate mul/add, no FMA)
//   vx = rn(rn(rn(x - idx) + 1) * DX);  sx = rn(vx*vx)
//   d2 = rn(sx + sy);  dis = sqrt.rn(d2)
//   t  = trunc( rn( rn(dis * rn(1/1500)) * 12500000.0f ) )
// (XLA algsimp rewrites divide-by-constant -> multiply-by-reciprocal.)
//   out[b, iy, ix] = (image - min_b) / (max_b - min_b)
// ---------------------------------------------------------------------------

static constexpr float DXc   = 0.001f;
static constexpr float DYc   = 0.001f;
static constexpr float DTF   = (float)(1.0 / 12500000.0);
static constexpr float RCPVS = (float)(1.0 / 1500.0);          // rn(1/1500)
static constexpr float RCPDT = (float)(1.0 / (double)DTF);     // == 12500000.0f

// scratch: two sensor-half planes of un-normalized sums.
// plane (h*8 + b), pixel p = ix*256 + iy. Final image = plane0 + plane1.
__device__ float g_scratch[16 * 65536];
__device__ float g_pmn[64], g_pmx[64];   // per-(batch, chunk) partial min/max

// t = trunc( rn( rn(sqrt_rn(d2) * RCPVS) * RCPDT ) )
__device__ __forceinline__ int t_chain(float d2) {
    float dis = __fsqrt_rn(d2);
    float q1  = __fmul_rn(dis, RCPVS);
    float q2  = __fmul_rn(q1, RCPDT);
    return __float2int_rz(q2);
}

// ---------------------------------------------------------------------------
// Kernel 1: per-CTA 32x32 pixel tile x 64-sensor half, 256 threads.
// Pair-unrolled sensor loop: one barrier / one cp.async group per 2 sensors.
// Window range for a 32x32 tile <= 31*sqrt(2)*DX/VS/DT + pads < 512 floats,
// so with +/-8 sample padding the staged window provably covers every gather.
// ---------------------------------------------------------------------------
#define WCAP4 128                  // window capacity: 128 float4 = 512 floats
#define NSTG  4                    // pipeline depth (buffers) = 2 pairs
#define NSEN  64                   // sensors per CTA (half of 128)

__global__ void __launch_bounds__(256, 7)
das_main(const float* __restrict__ sd, const float* __restrict__ mask)
{
    __shared__ float win[NSTG][WCAP4 * 4];
    __shared__ __align__(16) float sxt[NSEN * 32];   // sx = rn(vx*vx) per (s, ix)
    __shared__ float syt[NSEN * 32];                 // sy = rn(vy*vy) per (s, iy)
    __shared__ float smx[NSEN], smy[NSEN];
    __shared__ int   swb[NSEN], swn[NSEN];

    const int zb  = blockIdx.z;
    const int b   = zb >> 1;             // batch
    const int s_base = (zb & 1) << 6;    // sensor half: 0 or 64
    const int ix0 = blockIdx.x * 32;     // 0-based pixel tile origin
    const int iy0 = blockIdx.y * 32;
    const int tid = threadIdx.x;
    const int iy_off = tid & 31;         // this thread's iy within the tile
    const int ixg    = tid >> 5;         // ix group 0..7 (4 ix each)

    // ---- phase A: per-sensor coordinates + staging window bounds -----------
    if (tid < NSEN) {
        int sg = s_base + tid;
        float mxv = mask[((b * 128 + sg) << 1) + 0];
        float myv = mask[((b * 128 + sg) << 1) + 1];
        // separate mul then add (no FMA) — matches HLO mul + add
        float xm = __fadd_rn(__fmul_rn(mxv, 1000.0f), 128.0f);
        float ym = __fadd_rn(__fmul_rn(myv, 1000.0f), 128.0f);
        smx[tid] = xm;
        smy[tid] = ym;

        // corner (1-based) idx values of this tile
        float xl = (float)(ix0 + 1), xh = (float)(ix0 + 32);
        float yl = (float)(iy0 + 1), yh = (float)(iy0 + 32);

        // max distance over tile: at a corner (monotone exact chain per corner)
        float ax0 = __fadd_rn(__fsub_rn(xm, xl), 1.0f);
        float ax1 = __fadd_rn(__fsub_rn(xm, xh), 1.0f);
        float ay0 = __fadd_rn(__fsub_rn(ym, yl), 1.0f);
        float ay1 = __fadd_rn(__fsub_rn(ym, yh), 1.0f);
        float vx0 = __fmul_rn(ax0, DXc), vx1 = __fmul_rn(ax1, DXc);
        float vy0 = __fmul_rn(ay0, DYc), vy1 = __fmul_rn(ay1, DYc);
        float sx0 = __fmul_rn(vx0, vx0), sx1 = __fmul_rn(vx1, vx1);
        float sy0 = __fmul_rn(vy0, vy0), sy1 = __fmul_rn(vy1, vy1);
        float d2max = __fadd_rn(fmaxf(sx0, sx1), fmaxf(sy0, sy1));

        // min distance over tile: continuous clamp (lower bound), pad covers slop
        float ux = xm + 1.0f, uy = ym + 1.0f;   // sensor position in idx units
        float exd = fmaxf(fmaxf(xl - ux, ux - xh), 0.0f);
        float eyd = fmaxf(fmaxf(yl - uy, uy - yh), 0.0f);
        float vmx = exd * DXc, vmy = eyd * DYc;
        float d2min = vmx * vmx + vmy * vmy;

        int tmin = t_chain(d2min) - 8; if (tmin < 0) tmin = 0;
        int tmax = t_chain(d2max) + 8; if (tmax > 16383) tmax = 16383;

        int wb  = tmin & ~3;                       // 16B-aligned base
        int n4  = ((tmax - wb + 1) + 3) >> 2;      // float4 count
        int mx4 = (16384 - wb) >> 2;
        if (n4 > mx4)   n4 = mx4;
        if (n4 > WCAP4) n4 = WCAP4;                // provably never binds (<=100)
        swb[tid] = wb;
        swn[tid] = n4;
    }
    __syncthreads();

    // ---- phase B: precompute sx / sy term tables (exact chains) ------------
    #pragma unroll
    for (int i = tid; i < NSEN * 32; i += 256) {
        int s = i >> 5, l = i & 31;
        float xm  = smx[s], ym = smy[s];
        float ixf = (float)(ix0 + l + 1);
        float iyf = (float)(iy0 + l + 1);
        float ax  = __fadd_rn(__fsub_rn(xm, ixf), 1.0f);
        float vx  = __fmul_rn(ax, DXc);
        sxt[i] = __fmul_rn(vx, vx);
        float ay  = __fadd_rn(__fsub_rn(ym, iyf), 1.0f);
        float vy  = __fmul_rn(ay, DYc);
        syt[i] = __fmul_rn(vy, vy);
    }
    __syncthreads();

    const float* row_base = sd + (size_t)b * 128 * 16384 + (size_t)s_base * 16384;

    auto stage = [&](int s) {   // caller guarantees tid < 128 (warps 0..3)
        const int bi = s & (NSTG - 1);
        int wb = swb[s];
        if (tid < swn[s]) {
            const float* g = row_base + (size_t)s * 16384 + wb + tid * 4;
            uint32_t sa = (uint32_t)__cvta_generic_to_shared(&win[bi][tid * 4]);
            asm volatile("cp.async.cg.shared.global [%0], [%1], 16;\n"
                         :: "r"(sa), "l"(g) : "memory");
        }
    };

    // prologue: stage pair 0 (sensors 0,1) as one group
    if (tid < 128) { stage(0); stage(1); }
    asm volatile("cp.async.commit_group;\n" ::: "memory");

    float acc0 = 0.0f, acc1 = 0.0f, acc2 = 0.0f, acc3 = 0.0f;

    for (int s = 0; s < NSEN; s += 2) {
        // one pending group at entry (pair s) — committed one full pair ago
        asm volatile("cp.async.wait_group 0;\n" ::: "memory");
        __syncthreads();   // pair s ready; everyone done reading pair s-1 buffers

        if (tid < 128) {
            if (s + 2 < NSEN) { stage(s + 2); stage(s + 3); }
        }
        asm volatile("cp.async.commit_group;\n" ::: "memory");  // keep count invariant

        const int sA = s, sB = s + 1;
        const float* wA = &win[sA & (NSTG - 1)][0] - swb[sA];   // pre-offset bases
        const float* wB = &win[sB & (NSTG - 1)][0] - swb[sB];
        float syA = syt[(sA << 5) + iy_off];                    // stride-1, no conflicts
        float syB = syt[(sB << 5) + iy_off];
        float4 sxA = *reinterpret_cast<const float4*>(sxt + (sA << 5) + (ixg << 2));
        float4 sxB = *reinterpret_cast<const float4*>(sxt + (sB << 5) + (ixg << 2));

        // rn(sx + sy), no FMA; window provably covers t: no clamps.
        // 8 independent chains -> ILP across the sqrt latency.
        int a0 = t_chain(__fadd_rn(sxA.x, syA));
        int a1 = t_chain(__fadd_rn(sxA.y, syA));
        int a2 = t_chain(__fadd_rn(sxA.z, syA));
        int a3 = t_chain(__fadd_rn(sxA.w, syA));
        int b0 = t_chain(__fadd_rn(sxB.x, syB));
        int b1 = t_chain(__fadd_rn(sxB.y, syB));
        int b2 = t_chain(__fadd_rn(sxB.z, syB));
        int b3 = t_chain(__fadd_rn(sxB.w, syB));
        acc0 = __fadd_rn(acc0, wA[a0]);
        acc1 = __fadd_rn(acc1, wA[a1]);
        acc2 = __fadd_rn(acc2, wA[a2]);
        acc3 = __fadd_rn(acc3, wA[a3]);
        acc0 = __fadd_rn(acc0, wB[b0]);
        acc1 = __fadd_rn(acc1, wB[b1]);
        acc2 = __fadd_rn(acc2, wB[b2]);
        acc3 = __fadd_rn(acc3, wB[b3]);
    }

    // write un-normalized partial sums: plane (half*8 + b)
    float* osc = g_scratch + ((zb & 1) * 8 + b) * 65536
               + (ix0 + ixg * 4) * 256 + iy0 + iy_off;
    osc[0]   = acc0;
    osc[256] = acc1;
    osc[512] = acc2;
    osc[768] = acc3;
}

// ---------------------------------------------------------------------------
// Kernel 2: per-(batch, chunk) partial min/max over plane0+plane1, coalesced.
// grid = 64 (8 batches x 8 chunks of 8192), 256 threads.
// ---------------------------------------------------------------------------
__global__ void __launch_bounds__(256)
das_minmax()
{
    __shared__ float rmn[256], rmx[256];
    const int b     = blockIdx.x >> 3;
    const int chunk = blockIdx.x & 7;
    const int tid   = threadIdx.x;
    const float* p0 = g_scratch + b * 65536 + chunk * 8192;
    const float* p1 = p0 + 8 * 65536;

    float mn =  3.402823466e38f;
    float mx = -3.402823466e38f;
    #pragma unroll 4
    for (int i = tid; i < 8192; i += 256) {
        float v = __fadd_rn(p0[i], p1[i]);
        mn = fminf(mn, v);
        mx = fmaxf(mx, v);
    }
    rmn[tid] = mn; rmx[tid] = mx;
    __syncthreads();
    for (int o = 128; o > 0; o >>= 1) {
        if (tid < o) {
            rmn[tid] = fminf(rmn[tid], rmn[tid + o]);
            rmx[tid] = fmaxf(rmx[tid], rmx[tid + o]);
        }
        __syncthreads();
    }
    if (tid == 0) { g_pmn[blockIdx.x] = rmn[0]; g_pmx[blockIdx.x] = rmx[0]; }
}

// ---------------------------------------------------------------------------
// Kernel 3: normalize + transpose via 32x32 smem tiles, coalesced both ways.
// grid = (64, 8): 64 tiles per batch. block 256 = 32x8.
// ---------------------------------------------------------------------------
__global__ void __launch_bounds__(256)
das_norm_t(float* __restrict__ out)
{
    __shared__ float tile[32][33];
    const int b  = blockIdx.y;
    const int tx = blockIdx.x & 7;   // ix tile
    const int ty = blockIdx.x >> 3;  // iy tile
    const int lx = threadIdx.x & 31;
    const int lr = threadIdx.x >> 5; // 0..7

    // reduce the 8 per-batch partials (redundant per CTA, trivial)
    float mn = g_pmn[b * 8 + 0], mx = g_pmx[b * 8 + 0];
    #pragma unroll
    for (int c = 1; c < 8; ++c) {
        mn = fminf(mn, g_pmn[b * 8 + c]);
        mx = fmaxf(mx, g_pmx[b * 8 + c]);
    }
    float den = __fsub_rn(mx, mn);

    const float* i0 = g_scratch + b * 65536;
    const float* i1 = i0 + 8 * 65536;
    // load: rows are ix (tx*32 + r), cols iy (ty*32 + lx) — coalesced
    #pragma unroll
    for (int r = lr; r < 32; r += 8) {
        int p = (tx * 32 + r) * 256 + ty * 32 + lx;
        tile[r][lx] = __fadd_rn(i0[p], i1[p]);   // same order as das_minmax
    }
    __syncthreads();

    float* ob = out + b * 65536;
    // store: out[b, iy, ix] — rows iy (ty*32 + r), cols ix (tx*32 + lx) — coalesced
    #pragma unroll
    for (int r = lr; r < 32; r += 8) {
        float v = tile[lx][r];
        ob[(ty * 32 + r) * 256 + tx * 32 + lx] = __fdiv_rn(__fsub_rn(v, mn), den);
    }
}

// ---------------------------------------------------------------------------
extern "C" void kernel_launch(void* const* d_in, const int* in_sizes, int n_in,
                              void* d_out, int out_size)
{
    const float* sd   = (const float*)d_in[0];   // (8,128,16384) f32
    const float* mask = (const float*)d_in[1];   // (8,128,2) f32
    float* out = (float*)d_out;                  // (8,256,256) f32

    // z = batch*2 + sensor-half: 1024 CTAs -> ~7/SM, single co-resident wave
    dim3 grid(8, 8, 16);
    das_main<<<grid, 256>>>(sd, mask);
    das_minmax<<<64, 256>>>();
    das_norm_t<<<dim3(64, 8), 256>>>(out);
}

// round 12
// speedup vs baseline: 2.9194x; 1.0052x over previous
#include <cuda_runtime.h>
#include <cstdint>

// ---------------------------------------------------------------------------
// DAS beamformer — replicates XLA's compiled f32 chain:
//   m  = rn(rn(mask*1000) + 128)                      (separate mul/add, no FMA)
//   vx = rn(rn(rn(x - idx) + 1) * DX);  sx = rn(vx*vx)
//   d2 = rn(sx + sy);  dis = sqrt.rn(d2)
//   t  = trunc( rn( rn(dis * rn(1/1500)) * 12500000.0f ) )
// (XLA algsimp rewrites divide-by-constant -> multiply-by-reciprocal.)
//   out[b, iy, ix] = (image - min_b) / (max_b - min_b)
// Inner loop uses a 1-Newton RSQ sqrt whose rounded result matches sqrt.rn
// except with probability ~2^-20 per op (expected <0.1 flipped gathers total).
// ---------------------------------------------------------------------------

static constexpr float DXc   = 0.001f;
static constexpr float DYc   = 0.001f;
static constexpr float DTF   = (float)(1.0 / 12500000.0);
static constexpr float RCPVS = (float)(1.0 / 1500.0);          // rn(1/1500)
static constexpr float RCPDT = (float)(1.0 / (double)DTF);     // == 12500000.0f

// scratch: two sensor-half planes of un-normalized sums.
// plane (h*8 + b), pixel p = ix*256 + iy. Final image = plane0 + plane1.
__device__ float g_scratch[16 * 65536];
__device__ float g_pmn[64], g_pmx[64];   // per-(batch, chunk) partial min/max

// exact chain (used for window bounds only)
__device__ __forceinline__ int t_chain(float d2) {
    float dis = __fsqrt_rn(d2);
    float q1  = __fmul_rn(dis, RCPVS);
    float q2  = __fmul_rn(q1, RCPDT);
    return __float2int_rz(q2);
}

// fast chain: RSQ + 1 Newton, then identical multiply chain.
// dis == rn(sqrt(d2)) except ~2^-20 probability 1-ulp cases (see header).
__device__ __forceinline__ int t_fast(float d2) {
    d2 = fmaxf(d2, 1e-30f);            // kill d2=0 -> inf/NaN corner (t=0 anyway)
    float r;
    asm("rsqrt.approx.f32 %0, %1;" : "=f"(r) : "f"(d2));
    float y   = __fmul_rn(d2, r);      // approx sqrt
    float h   = __fmul_rn(0.5f, r);
    float e   = __fmaf_rn(-y, y, d2);  // exact residual via FMA
    float dis = __fmaf_rn(e, h, y);    // one Newton step, single final round
    float q1  = __fmul_rn(dis, RCPVS);
    float q2  = __fmul_rn(q1, RCPDT);
    return __float2int_rz(q2);
}

// ---------------------------------------------------------------------------
// Kernel 1: per-CTA 32x32 pixel tile x 64-sensor half, 256 threads.
// Pair-unrolled sensor loop: one barrier / one cp.async group per 2 sensors.
// Window range for a 32x32 tile <= 31*sqrt(2)*DX/VS/DT + pads < 512 floats,
// so with +/-8 sample padding the staged window provably covers every gather
// (pad also absorbs the <=1-ulp t difference between t_fast and t_chain).
// ---------------------------------------------------------------------------
#define WCAP4 128                  // window capacity: 128 float4 = 512 floats
#define NSTG  4                    // pipeline depth (buffers) = 2 pairs
#define NSEN  64                   // sensors per CTA (half of 128)

__global__ void __launch_bounds__(256, 7)
das_main(const float* __restrict__ sd, const float* __restrict__ mask)
{
    __shared__ float win[NSTG][WCAP4 * 4];
    __shared__ __align__(16) float sxt[NSEN * 32];   // sx = rn(vx*vx) per (s, ix)
    __shared__ float syt[NSEN * 32];                 // sy = rn(vy*vy) per (s, iy)
    __shared__ float smx[NSEN], smy[NSEN];
    __shared__ int   swb[NSEN], swn[NSEN];

    const int zb  = blockIdx.z;
    const int b   = zb >> 1;             // batch
    const int s_base = (zb & 1) << 6;    // sensor half: 0 or 64
    const int ix0 = blockIdx.x * 32;     // 0-based pixel tile origin
    const int iy0 = blockIdx.y * 32;
    const int tid = threadIdx.x;
    const int iy_off = tid & 31;         // this thread's iy within the tile
    const int ixg    = tid >> 5;         // ix group 0..7 (4 ix each)

    // ---- phase A: per-sensor coordinates + staging window bounds -----------
    if (tid < NSEN) {
        int sg = s_base + tid;
        float mxv = mask[((b * 128 + sg) << 1) + 0];
        float myv = mask[((b * 128 + sg) << 1) + 1];
        // separate mul then add (no FMA) — matches HLO mul + add
        float xm = __fadd_rn(__fmul_rn(mxv, 1000.0f), 128.0f);
        float ym = __fadd_rn(__fmul_rn(myv, 1000.0f), 128.0f);
        smx[tid] = xm;
        smy[tid] = ym;

        // corner (1-based) idx values of this tile
        float xl = (float)(ix0 + 1), xh = (float)(ix0 + 32);
        float yl = (float)(iy0 + 1), yh = (float)(iy0 + 32);

        // max distance over tile: at a corner (monotone exact chain per corner)
        float ax0 = __fadd_rn(__fsub_rn(xm, xl), 1.0f);
        float ax1 = __fadd_rn(__fsub_rn(xm, xh), 1.0f);
        float ay0 = __fadd_rn(__fsub_rn(ym, yl), 1.0f);
        float ay1 = __fadd_rn(__fsub_rn(ym, yh), 1.0f);
        float vx0 = __fmul_rn(ax0, DXc), vx1 = __fmul_rn(ax1, DXc);
        float vy0 = __fmul_rn(ay0, DYc), vy1 = __fmul_rn(ay1, DYc);
        float sx0 = __fmul_rn(vx0, vx0), sx1 = __fmul_rn(vx1, vx1);
        float sy0 = __fmul_rn(vy0, vy0), sy1 = __fmul_rn(vy1, vy1);
        float d2max = __fadd_rn(fmaxf(sx0, sx1), fmaxf(sy0, sy1));

        // min distance over tile: continuous clamp (lower bound), pad covers slop
        float ux = xm + 1.0f, uy = ym + 1.0f;   // sensor position in idx units
        float exd = fmaxf(fmaxf(xl - ux, ux - xh), 0.0f);
        float eyd = fmaxf(fmaxf(yl - uy, uy - yh), 0.0f);
        float vmx = exd * DXc, vmy = eyd * DYc;
        float d2min = vmx * vmx + vmy * vmy;

        int tmin = t_chain(d2min) - 8; if (tmin < 0) tmin = 0;
        int tmax = t_chain(d2max) + 8; if (tmax > 16383) tmax = 16383;

        int wb  = tmin & ~3;                       // 16B-aligned base
        int n4  = ((tmax - wb + 1) + 3) >> 2;      // float4 count
        int mx4 = (16384 - wb) >> 2;
        if (n4 > mx4)   n4 = mx4;
        if (n4 > WCAP4) n4 = WCAP4;                // provably never binds (<=100)
        swb[tid] = wb;
        swn[tid] = n4;
    }
    __syncthreads();

    // ---- phase B: precompute sx / sy term tables (exact chains) ------------
    #pragma unroll
    for (int i = tid; i < NSEN * 32; i += 256) {
        int s = i >> 5, l = i & 31;
        float xm  = smx[s], ym = smy[s];
        float ixf = (float)(ix0 + l + 1);
        float iyf = (float)(iy0 + l + 1);
        float ax  = __fadd_rn(__fsub_rn(xm, ixf), 1.0f);
        float vx  = __fmul_rn(ax, DXc);
        sxt[i] = __fmul_rn(vx, vx);
        float ay  = __fadd_rn(__fsub_rn(ym, iyf), 1.0f);
        float vy  = __fmul_rn(ay, DYc);
        syt[i] = __fmul_rn(vy, vy);
    }
    __syncthreads();

    const float* row_base = sd + (size_t)b * 128 * 16384 + (size_t)s_base * 16384;

    auto stage = [&](int s) {   // caller guarantees tid < 128 (warps 0..3)
        const int bi = s & (NSTG - 1);
        int wb = swb[s];
        if (tid < swn[s]) {
            const float* g = row_base + (size_t)s * 16384 + wb + tid * 4;
            uint32_t sa = (uint32_t)__cvta_generic_to_shared(&win[bi][tid * 4]);
            asm volatile("cp.async.cg.shared.global [%0], [%1], 16;\n"
                         :: "r"(sa), "l"(g) : "memory");
        }
    };

    // prologue: stage pair 0 (sensors 0,1) as one group
    if (tid < 128) { stage(0); stage(1); }
    asm volatile("cp.async.commit_group;\n" ::: "memory");

    float acc0 = 0.0f, acc1 = 0.0f, acc2 = 0.0f, acc3 = 0.0f;

    for (int s = 0; s < NSEN; s += 2) {
        // one pending group at entry (pair s) — committed one full pair ago
        asm volatile("cp.async.wait_group 0;\n" ::: "memory");
        __syncthreads();   // pair s ready; everyone done reading pair s-1 buffers

        if (tid < 128) {
            if (s + 2 < NSEN) { stage(s + 2); stage(s + 3); }
        }
        asm volatile("cp.async.commit_group;\n" ::: "memory");  // keep count invariant

        const int sA = s, sB = s + 1;
        const float* wA = &win[sA & (NSTG - 1)][0] - swb[sA];   // pre-offset bases
        const float* wB = &win[sB & (NSTG - 1)][0] - swb[sB];
        float syA = syt[(sA << 5) + iy_off];                    // stride-1, no conflicts
        float syB = syt[(sB << 5) + iy_off];
        float4 sxA = *reinterpret_cast<const float4*>(sxt + (sA << 5) + (ixg << 2));
        float4 sxB = *reinterpret_cast<const float4*>(sxt + (sB << 5) + (ixg << 2));

        // rn(sx + sy), no FMA; window provably covers t: no clamps.
        // 8 independent chains -> ILP across the RSQ latency.
        int a0 = t_fast(__fadd_rn(sxA.x, syA));
        int a1 = t_fast(__fadd_rn(sxA.y, syA));
        int a2 = t_fast(__fadd_rn(sxA.z, syA));
        int a3 = t_fast(__fadd_rn(sxA.w, syA));
        int b0 = t_fast(__fadd_rn(sxB.x, syB));
        int b1 = t_fast(__fadd_rn(sxB.y, syB));
        int b2 = t_fast(__fadd_rn(sxB.z, syB));
        int b3 = t_fast(__fadd_rn(sxB.w, syB));
        acc0 = __fadd_rn(acc0, wA[a0]);
        acc1 = __fadd_rn(acc1, wA[a1]);
        acc2 = __fadd_rn(acc2, wA[a2]);
        acc3 = __fadd_rn(acc3, wA[a3]);
        acc0 = __fadd_rn(acc0, wB[b0]);
        acc1 = __fadd_rn(acc1, wB[b1]);
        acc2 = __fadd_rn(acc2, wB[b2]);
        acc3 = __fadd_rn(acc3, wB[b3]);
    }

    // write un-normalized partial sums: plane (half*8 + b)
    float* osc = g_scratch + ((zb & 1) * 8 + b) * 65536
               + (ix0 + ixg * 4) * 256 + iy0 + iy_off;
    osc[0]   = acc0;
    osc[256] = acc1;
    osc[512] = acc2;
    osc[768] = acc3;
}

// ---------------------------------------------------------------------------
// Kernel 2: per-(batch, chunk) partial min/max over plane0+plane1, coalesced.
// grid = 64 (8 batches x 8 chunks of 8192), 256 threads.
// ---------------------------------------------------------------------------
__global__ void __launch_bounds__(256)
das_minmax()
{
    __shared__ float rmn[256], rmx[256];
    const int b     = blockIdx.x >> 3;
    const int chunk = blockIdx.x & 7;
    const int tid   = threadIdx.x;
    const float* p0 = g_scratch + b * 65536 + chunk * 8192;
    const float* p1 = p0 + 8 * 65536;

    float mn =  3.402823466e38f;
    float mx = -3.402823466e38f;
    #pragma unroll 4
    for (int i = tid; i < 8192; i += 256) {
        float v = __fadd_rn(p0[i], p1[i]);
        mn = fminf(mn, v);
        mx = fmaxf(mx, v);
    }
    rmn[tid] = mn; rmx[tid] = mx;
    __syncthreads();
    for (int o = 128; o > 0; o >>= 1) {
        if (tid < o) {
            rmn[tid] = fminf(rmn[tid], rmn[tid + o]);
            rmx[tid] = fmaxf(rmx[tid], rmx[tid + o]);
        }
        __syncthreads();
    }
    if (tid == 0) { g_pmn[blockIdx.x] = rmn[0]; g_pmx[blockIdx.x] = rmx[0]; }
}

// ---------------------------------------------------------------------------
// Kernel 3: normalize + transpose via 32x32 smem tiles, coalesced both ways.
// grid = (64, 8): 64 tiles per batch. block 256 = 32x8.
// ---------------------------------------------------------------------------
__global__ void __launch_bounds__(256)
das_norm_t(float* __restrict__ out)
{
    __shared__ float tile[32][33];
    const int b  = blockIdx.y;
    const int tx = blockIdx.x & 7;   // ix tile
    const int ty = blockIdx.x >> 3;  // iy tile
    const int lx = threadIdx.x & 31;
    const int lr = threadIdx.x >> 5; // 0..7

    // reduce the 8 per-batch partials (redundant per CTA, trivial)
    float mn = g_pmn[b * 8 + 0], mx = g_pmx[b * 8 + 0];
    #pragma unroll
    for (int c = 1; c < 8; ++c) {
        mn = fminf(mn, g_pmn[b * 8 + c]);
        mx = fmaxf(mx, g_pmx[b * 8 + c]);
    }
    float den = __fsub_rn(mx, mn);

    const float* i0 = g_scratch + b * 65536;
    const float* i1 = i0 + 8 * 65536;
    // load: rows are ix (tx*32 + r), cols iy (ty*32 + lx) — coalesced
    #pragma unroll
    for (int r = lr; r < 32; r += 8) {
        int p = (tx * 32 + r) * 256 + ty * 32 + lx;
        tile[r][lx] = __fadd_rn(i0[p], i1[p]);   // same order as das_minmax
    }
    __syncthreads();

    float* ob = out + b * 65536;
    // store: out[b, iy, ix] — rows iy (ty*32 + r), cols ix (tx*32 + lx) — coalesced
    #pragma unroll
    for (int r = lr; r < 32; r += 8) {
        float v = tile[lx][r];
        ob[(ty * 32 + r) * 256 + tx * 32 + lx] = __fdiv_rn(__fsub_rn(v, mn), den);
    }
}

// ---------------------------------------------------------------------------
extern "C" void kernel_launch(void* const* d_in, const int* in_sizes, int n_in,
                              void* d_out, int out_size)
{
    const float* sd   = (const float*)d_in[0];   // (8,128,16384) f32
    const float* mask = (const float*)d_in[1];   // (8,128,2) f32
    float* out = (float*)d_out;                  // (8,256,256) f32

    // z = batch*2 + sensor-half: 1024 CTAs -> ~7/SM, single co-resident wave
    dim3 grid(8, 8, 16);
    das_main<<<grid, 256>>>(sd, mask);
    das_minmax<<<64, 256>>>();
    das_norm_t<<<dim3(64, 8), 256>>>(out);
}

// round 13
// speedup vs baseline: 3.3190x; 1.1369x over previous
#include <cuda_runtime.h>
#include <cstdint>

// ---------------------------------------------------------------------------
// DAS beamformer — replicates XLA's compiled f32 chain:
//   m  = rn(rn(mask*1000) + 128)                      (separate mul/add, no FMA)
//   vx = rn(rn(rn(x - idx) + 1) * DX);  sx = rn(vx*vx)
//   d2 = rn(sx + sy);  dis = sqrt.rn(d2)
//   t  = trunc( rn( rn(dis * rn(1/1500)) * 12500000.0f ) )
// (XLA algsimp rewrites divide-by-constant -> multiply-by-reciprocal.)
//   out[b, iy, ix] = (image - min_b) / (max_b - min_b)
// Inner loop: packed f32x2 chain (2 gathers per sequence). Per-component the
// ops are IEEE RN, identical to scalar. sqrt via RSQ + 1 Newton matches
// sqrt.rn except ~2^-20 probability 1-ulp cases (<0.1 expected flips total).
// ---------------------------------------------------------------------------

static constexpr float DXc   = 0.001f;
static constexpr float DYc   = 0.001f;
static constexpr float DTF   = (float)(1.0 / 12500000.0);
static constexpr float RCPVS = (float)(1.0 / 1500.0);          // rn(1/1500)
static constexpr float RCPDT = (float)(1.0 / (double)DTF);     // == 12500000.0f

// scratch: two sensor-half planes of un-normalized sums.
// plane (h*8 + b), pixel p = ix*256 + iy. Final image = plane0 + plane1.
__device__ float g_scratch[16 * 65536];
__device__ float g_pmn[64], g_pmx[64];   // per-(batch, chunk) partial min/max

// exact chain (used for window bounds only)
__device__ __forceinline__ int t_chain(float d2) {
    float dis = __fsqrt_rn(d2);
    float q1  = __fmul_rn(dis, RCPVS);
    float q2  = __fmul_rn(q1, RCPDT);
    return __float2int_rz(q2);
}

__device__ __forceinline__ uint64_t pack2(float a, float b) {
    uint64_t v; asm("mov.b64 %0, {%1, %2};" : "=l"(v) : "f"(a), "f"(b)); return v;
}

// Packed 2-wide t computation: d2 = sx + sy; dis = RSQ+Newton sqrt;
// t = trunc(dis * RCPVS * RCPDT). All packed ops are per-component IEEE RN.
// Caller guarantees d2 > 0 (sxt table is clamped to >= 1e-30).
__device__ __forceinline__ void t2_fast(float sxa, float sxb, uint64_t sy2,
                                        uint64_t half2, uint64_t sgn2,
                                        uint64_t rcpvs2, uint64_t rcpdt2,
                                        int &ta, int &tb)
{
    asm("{\n\t"
        ".reg .f32 lo, hi, rl, rh, qa, qb;\n\t"
        ".reg .b64 sx2, d2, r2, y2, h2, e2, ds, p1, p2, yn;\n\t"
        "mov.b64 sx2, {%2, %3};\n\t"
        "add.rn.f32x2 d2, sx2, %4;\n\t"
        "mov.b64 {lo, hi}, d2;\n\t"
        "rsqrt.approx.f32 rl, lo;\n\t"
        "rsqrt.approx.f32 rh, hi;\n\t"
        "mov.b64 r2, {rl, rh};\n\t"
        "mul.rn.f32x2 y2, d2, r2;\n\t"
        "mul.rn.f32x2 h2, r2, %5;\n\t"
        "xor.b64 yn, y2, %6;\n\t"
        "fma.rn.f32x2 e2, yn, y2, d2;\n\t"
        "fma.rn.f32x2 ds, e2, h2, y2;\n\t"
        "mul.rn.f32x2 p1, ds, %7;\n\t"
        "mul.rn.f32x2 p2, p1, %8;\n\t"
        "mov.b64 {qa, qb}, p2;\n\t"
        "cvt.rzi.s32.f32 %0, qa;\n\t"
        "cvt.rzi.s32.f32 %1, qb;\n\t"
        "}"
        : "=r"(ta), "=r"(tb)
        : "f"(sxa), "f"(sxb), "l"(sy2), "l"(half2), "l"(sgn2),
          "l"(rcpvs2), "l"(rcpdt2));
}

// ---------------------------------------------------------------------------
// Kernel 1: per-CTA 32x32 pixel tile x 64-sensor half, 256 threads.
// Pair-unrolled sensor loop: one barrier / one cp.async group per 2 sensors.
// Window range for a 32x32 tile <= 31*sqrt(2)*DX/VS/DT + pads < 512 floats,
// so with +/-8 sample padding the staged window provably covers every gather
// (pad also absorbs the <=1-ulp t difference between fast and exact chains).
// ---------------------------------------------------------------------------
#define WCAP4 128                  // window capacity: 128 float4 = 512 floats
#define NSTG  4                    // pipeline depth (buffers) = 2 pairs
#define NSEN  64                   // sensors per CTA (half of 128)

__global__ void __launch_bounds__(256, 7)
das_main(const float* __restrict__ sd, const float* __restrict__ mask)
{
    __shared__ float win[NSTG][WCAP4 * 4];
    __shared__ __align__(16) float sxt[NSEN * 32];   // sx = max(rn(vx*vx), 1e-30)
    __shared__ float syt[NSEN * 32];                 // sy = rn(vy*vy) per (s, iy)
    __shared__ float smx[NSEN], smy[NSEN];
    __shared__ int   swb[NSEN], swn[NSEN];

    const int zb  = blockIdx.z;
    const int b   = zb >> 1;             // batch
    const int s_base = (zb & 1) << 6;    // sensor half: 0 or 64
    const int ix0 = blockIdx.x * 32;     // 0-based pixel tile origin
    const int iy0 = blockIdx.y * 32;
    const int tid = threadIdx.x;
    const int iy_off = tid & 31;         // this thread's iy within the tile
    const int ixg    = tid >> 5;         // ix group 0..7 (4 ix each)

    // packed constants for the f32x2 chain
    const uint32_t rvu = __float_as_uint(RCPVS);
    const uint32_t rdu = __float_as_uint(RCPDT);
    const uint64_t RCPVS2 = ((uint64_t)rvu << 32) | rvu;
    const uint64_t RCPDT2 = ((uint64_t)rdu << 32) | rdu;
    const uint64_t HALF2  = 0x3F0000003F000000ULL;   // {0.5f, 0.5f}
    const uint64_t SGN2   = 0x8000000080000000ULL;   // sign bits

    // ---- phase A: per-sensor coordinates + staging window bounds -----------
    if (tid < NSEN) {
        int sg = s_base + tid;
        float mxv = mask[((b * 128 + sg) << 1) + 0];
        float myv = mask[((b * 128 + sg) << 1) + 1];
        // separate mul then add (no FMA) — matches HLO mul + add
        float xm = __fadd_rn(__fmul_rn(mxv, 1000.0f), 128.0f);
        float ym = __fadd_rn(__fmul_rn(myv, 1000.0f), 128.0f);
        smx[tid] = xm;
        smy[tid] = ym;

        // corner (1-based) idx values of this tile
        float xl = (float)(ix0 + 1), xh = (float)(ix0 + 32);
        float yl = (float)(iy0 + 1), yh = (float)(iy0 + 32);

        // max distance over tile: at a corner (monotone exact chain per corner)
        float ax0 = __fadd_rn(__fsub_rn(xm, xl), 1.0f);
        float ax1 = __fadd_rn(__fsub_rn(xm, xh), 1.0f);
        float ay0 = __fadd_rn(__fsub_rn(ym, yl), 1.0f);
        float ay1 = __fadd_rn(__fsub_rn(ym, yh), 1.0f);
        float vx0 = __fmul_rn(ax0, DXc), vx1 = __fmul_rn(ax1, DXc);
        float vy0 = __fmul_rn(ay0, DYc), vy1 = __fmul_rn(ay1, DYc);
        float sx0 = __fmul_rn(vx0, vx0), sx1 = __fmul_rn(vx1, vx1);
        float sy0 = __fmul_rn(vy0, vy0), sy1 = __fmul_rn(vy1, vy1);
        float d2max = __fadd_rn(fmaxf(sx0, sx1), fmaxf(sy0, sy1));

        // min distance over tile: continuous clamp (lower bound), pad covers slop
        float ux = xm + 1.0f, uy = ym + 1.0f;   // sensor position in idx units
        float exd = fmaxf(fmaxf(xl - ux, ux - xh), 0.0f);
        float eyd = fmaxf(fmaxf(yl - uy, uy - yh), 0.0f);
        float vmx = exd * DXc, vmy = eyd * DYc;
        float d2min = vmx * vmx + vmy * vmy;

        int tmin = t_chain(d2min) - 8; if (tmin < 0) tmin = 0;
        int tmax = t_chain(d2max) + 8; if (tmax > 16383) tmax = 16383;

        int wb  = tmin & ~3;                       // 16B-aligned base
        int n4  = ((tmax - wb + 1) + 3) >> 2;      // float4 count
        int mx4 = (16384 - wb) >> 2;
        if (n4 > mx4)   n4 = mx4;
        if (n4 > WCAP4) n4 = WCAP4;                // provably never binds (<=100)
        swb[tid] = wb;
        swn[tid] = n4;
    }
    __syncthreads();

    // ---- phase B: precompute sx / sy term tables (exact chains) ------------
    #pragma unroll
    for (int i = tid; i < NSEN * 32; i += 256) {
        int s = i >> 5, l = i & 31;
        float xm  = smx[s], ym = smy[s];
        float ixf = (float)(ix0 + l + 1);
        float iyf = (float)(iy0 + l + 1);
        float ax  = __fadd_rn(__fsub_rn(xm, ixf), 1.0f);
        float vx  = __fmul_rn(ax, DXc);
        // clamp: changes d2 only when sx is 0/denormal, where t=0 either way.
        sxt[i] = fmaxf(__fmul_rn(vx, vx), 1e-30f);
        float ay  = __fadd_rn(__fsub_rn(ym, iyf), 1.0f);
        float vy  = __fmul_rn(ay, DYc);
        syt[i] = __fmul_rn(vy, vy);
    }
    __syncthreads();

    const float* row_base = sd + (size_t)b * 128 * 16384 + (size_t)s_base * 16384;

    auto stage = [&](int s) {   // caller guarantees tid < 128 (warps 0..3)
        const int bi = s & (NSTG - 1);
        int wb = swb[s];
        if (tid < swn[s]) {
            const float* g = row_base + (size_t)s * 16384 + wb + tid * 4;
            uint32_t sa = (uint32_t)__cvta_generic_to_shared(&win[bi][tid * 4]);
            asm volatile("cp.async.cg.shared.global [%0], [%1], 16;\n"
                         :: "r"(sa), "l"(g) : "memory");
        }
    };

    // prologue: stage pair 0 (sensors 0,1) as one group
    if (tid < 128) { stage(0); stage(1); }
    asm volatile("cp.async.commit_group;\n" ::: "memory");

    float acc0 = 0.0f, acc1 = 0.0f, acc2 = 0.0f, acc3 = 0.0f;

    for (int s = 0; s < NSEN; s += 2) {
        // one pending group at entry (pair s) — committed one full pair ago
        asm volatile("cp.async.wait_group 0;\n" ::: "memory");
        __syncthreads();   // pair s ready; everyone done reading pair s-1 buffers

        if (tid < 128) {
            if (s + 2 < NSEN) { stage(s + 2); stage(s + 3); }
        }
        asm volatile("cp.async.commit_group;\n" ::: "memory");  // keep count invariant

        const int sA = s, sB = s + 1;
        const float* wA = &win[sA & (NSTG - 1)][0] - swb[sA];   // pre-offset bases
        const float* wB = &win[sB & (NSTG - 1)][0] - swb[sB];
        float syA = syt[(sA << 5) + iy_off];                    // stride-1, no conflicts
        float syB = syt[(sB << 5) + iy_off];
        uint64_t syA2 = pack2(syA, syA);
        uint64_t syB2 = pack2(syB, syB);
        float4 sxA = *reinterpret_cast<const float4*>(sxt + (sA << 5) + (ixg << 2));
        float4 sxB = *reinterpret_cast<const float4*>(sxt + (sB << 5) + (ixg << 2));

        // packed f32x2 chains: per-component identical to the scalar RN chain.
        int a0, a1, a2, a3, b0, b1, b2, b3;
        t2_fast(sxA.x, sxA.y, syA2, HALF2, SGN2, RCPVS2, RCPDT2, a0, a1);
        t2_fast(sxA.z, sxA.w, syA2, HALF2, SGN2, RCPVS2, RCPDT2, a2, a3);
        t2_fast(sxB.x, sxB.y, syB2, HALF2, SGN2, RCPVS2, RCPDT2, b0, b1);
        t2_fast(sxB.z, sxB.w, syB2, HALF2, SGN2, RCPVS2, RCPDT2, b2, b3);
        acc0 = __fadd_rn(acc0, wA[a0]);
        acc1 = __fadd_rn(acc1, wA[a1]);
        acc2 = __fadd_rn(acc2, wA[a2]);
        acc3 = __fadd_rn(acc3, wA[a3]);
        acc0 = __fadd_rn(acc0, wB[b0]);
        acc1 = __fadd_rn(acc1, wB[b1]);
        acc2 = __fadd_rn(acc2, wB[b2]);
        acc3 = __fadd_rn(acc3, wB[b3]);
    }

    // write un-normalized partial sums: plane (half*8 + b)
    float* osc = g_scratch + ((zb & 1) * 8 + b) * 65536
               + (ix0 + ixg * 4) * 256 + iy0 + iy_off;
    osc[0]   = acc0;
    osc[256] = acc1;
    osc[512] = acc2;
    osc[768] = acc3;
}

// ---------------------------------------------------------------------------
// Kernel 2: per-(batch, chunk) partial min/max over plane0+plane1, coalesced.
// grid = 64 (8 batches x 8 chunks of 8192), 256 threads.
// ---------------------------------------------------------------------------
__global__ void __launch_bounds__(256)
das_minmax()
{
    __shared__ float rmn[256], rmx[256];
    const int b     = blockIdx.x >> 3;
    const int chunk = blockIdx.x & 7;
    const int tid   = threadIdx.x;
    const float* p0 = g_scratch + b * 65536 + chunk * 8192;
    const float* p1 = p0 + 8 * 65536;

    float mn =  3.402823466e38f;
    float mx = -3.402823466e38f;
    #pragma unroll 4
    for (int i = tid; i < 8192; i += 256) {
        float v = __fadd_rn(p0[i], p1[i]);
        mn = fminf(mn, v);
        mx = fmaxf(mx, v);
    }
    rmn[tid] = mn; rmx[tid] = mx;
    __syncthreads();
    for (int o = 128; o > 0; o >>= 1) {
        if (tid < o) {
            rmn[tid] = fminf(rmn[tid], rmn[tid + o]);
            rmx[tid] = fmaxf(rmx[tid], rmx[tid + o]);
        }
        __syncthreads();
    }
    if (tid == 0) { g_pmn[blockIdx.x] = rmn[0]; g_pmx[blockIdx.x] = rmx[0]; }
}

// ---------------------------------------------------------------------------
// Kernel 3: normalize + transpose via 32x32 smem tiles, coalesced both ways.
// grid = (64, 8): 64 tiles per batch. block 256 = 32x8.
// ---------------------------------------------------------------------------
__global__ void __launch_bounds__(256)
das_norm_t(float* __restrict__ out)
{
    __shared__ float tile[32][33];
    const int b  = blockIdx.y;
    const int tx = blockIdx.x & 7;   // ix tile
    const int ty = blockIdx.x >> 3;  // iy tile
    const int lx = threadIdx.x & 31;
    const int lr = threadIdx.x >> 5; // 0..7

    // reduce the 8 per-batch partials (redundant per CTA, trivial)
    float mn = g_pmn[b * 8 + 0], mx = g_pmx[b * 8 + 0];
    #pragma unroll
    for (int c = 1; c < 8; ++c) {
        mn = fminf(mn, g_pmn[b * 8 + c]);
        mx = fmaxf(mx, g_pmx[b * 8 + c]);
    }
    float den = __fsub_rn(mx, mn);

    const float* i0 = g_scratch + b * 65536;
    const float* i1 = i0 + 8 * 65536;
    // load: rows are ix (tx*32 + r), cols iy (ty*32 + lx) — coalesced
    #pragma unroll
    for (int r = lr; r < 32; r += 8) {
        int p = (tx * 32 + r) * 256 + ty * 32 + lx;
        tile[r][lx] = __fadd_rn(i0[p], i1[p]);   // same order as das_minmax
    }
    __syncthreads();

    float* ob = out + b * 65536;
    // store: out[b, iy, ix] — rows iy (ty*32 + r), cols ix (tx*32 + lx) — coalesced
    #pragma unroll
    for (int r = lr; r < 32; r += 8) {
        float v = tile[lx][r];
        ob[(ty * 32 + r) * 256 + tx * 32 + lx] = __fdiv_rn(__fsub_rn(v, mn), den);
    }
}

// ---------------------------------------------------------------------------
extern "C" void kernel_launch(void* const* d_in, const int* in_sizes, int n_in,
                              void* d_out, int out_size)
{
    const float* sd   = (const float*)d_in[0];   // (8,128,16384) f32
    const float* mask = (const float*)d_in[1];   // (8,128,2) f32
    float* out = (float*)d_out;                  // (8,256,256) f32

    // z = batch*2 + sensor-half: 1024 CTAs -> ~7/SM, single co-resident wave
    dim3 grid(8, 8, 16);
    das_main<<<grid, 256>>>(sd, mask);
    das_minmax<<<64, 256>>>();
    das_norm_t<<<dim3(64, 8), 256>>>(out);
}

// round 14
// speedup vs baseline: 3.4127x; 1.0283x over previous
#include <cuda_runtime.h>
#include <cstdint>

// ---------------------------------------------------------------------------
// DAS beamformer — replicates XLA's compiled f32 chain:
//   m  = rn(rn(mask*1000) + 128)                      (separate mul/add, no FMA)
//   vx = rn(rn(rn(x - idx) + 1) * DX);  sx = rn(vx*vx)
//   d2 = rn(sx + sy);  dis = sqrt.rn(d2)
//   t  = trunc( rn( rn(dis * rn(1/1500)) * 12500000.0f ) )
// (XLA algsimp rewrites divide-by-constant -> multiply-by-reciprocal.)
//   out[b, iy, ix] = (image - min_b) / (max_b - min_b)
// Inner loop: packed f32x2 chain (2 gathers per sequence). Per-component the
// ops are IEEE RN, identical to scalar. sqrt via RSQ + 1 Newton matches
// sqrt.rn except ~2^-20 probability 1-ulp cases (<0.1 expected flips total).
// ---------------------------------------------------------------------------

static constexpr float DXc   = 0.001f;
static constexpr float DYc   = 0.001f;
static constexpr float DTF   = (float)(1.0 / 12500000.0);
static constexpr float RCPVS = (float)(1.0 / 1500.0);          // rn(1/1500)
static constexpr float RCPDT = (float)(1.0 / (double)DTF);     // == 12500000.0f

// scratch: two sensor-half planes of un-normalized sums.
// plane (h*8 + b), pixel p = ix*256 + iy. Final image = plane0 + plane1.
__device__ float g_scratch[16 * 65536];
__device__ float g_pmn[64], g_pmx[64];   // per-(batch, chunk) partial min/max

// exact chain (used for window bounds only)
__device__ __forceinline__ int t_chain(float d2) {
    float dis = __fsqrt_rn(d2);
    float q1  = __fmul_rn(dis, RCPVS);
    float q2  = __fmul_rn(q1, RCPDT);
    return __float2int_rz(q2);
}

__device__ __forceinline__ uint64_t pack2(float a, float b) {
    uint64_t v; asm("mov.b64 %0, {%1, %2};" : "=l"(v) : "f"(a), "f"(b)); return v;
}

// Packed 2-wide t computation: d2 = sx + sy; dis = RSQ+Newton sqrt;
// t = trunc(dis * RCPVS * RCPDT). All packed ops are per-component IEEE RN.
// Caller guarantees d2 > 0 (sxt table is clamped to >= 1e-30).
__device__ __forceinline__ void t2_fast(uint64_t sx2, uint64_t sy2,
                                        uint64_t half2, uint64_t sgn2,
                                        uint64_t rcpvs2, uint64_t rcpdt2,
                                        int &ta, int &tb)
{
    asm("{\n\t"
        ".reg .f32 lo, hi, rl, rh, qa, qb;\n\t"
        ".reg .b64 d2, r2, y2, h2, e2, ds, p1, p2, yn;\n\t"
        "add.rn.f32x2 d2, %2, %3;\n\t"
        "mov.b64 {lo, hi}, d2;\n\t"
        "rsqrt.approx.f32 rl, lo;\n\t"
        "rsqrt.approx.f32 rh, hi;\n\t"
        "mov.b64 r2, {rl, rh};\n\t"
        "mul.rn.f32x2 y2, d2, r2;\n\t"
        "mul.rn.f32x2 h2, r2, %4;\n\t"
        "xor.b64 yn, y2, %5;\n\t"
        "fma.rn.f32x2 e2, yn, y2, d2;\n\t"
        "fma.rn.f32x2 ds, e2, h2, y2;\n\t"
        "mul.rn.f32x2 p1, ds, %6;\n\t"
        "mul.rn.f32x2 p2, p1, %7;\n\t"
        "mov.b64 {qa, qb}, p2;\n\t"
        "cvt.rzi.s32.f32 %0, qa;\n\t"
        "cvt.rzi.s32.f32 %1, qb;\n\t"
        "}"
        : "=r"(ta), "=r"(tb)
        : "l"(sx2), "l"(sy2), "l"(half2), "l"(sgn2),
          "l"(rcpvs2), "l"(rcpdt2));
}

// ---------------------------------------------------------------------------
// Kernel 1: per-CTA 32x32 pixel tile x 64-sensor half, 256 threads.
// Quad-unrolled sensor loop: one barrier / one cp.async group per 4 sensors,
// 8 window buffers (staging quad q+1 while computing quad q).
// Window range for a 32x32 tile <= 31*sqrt(2)*DX/VS/DT (365.4) + 16 pad + 3
// align < 448 floats, so WCAP4=112 provably covers every gather (the pad also
// absorbs the <=1-ulp t difference between fast and exact chains).
// ---------------------------------------------------------------------------
#define WCAP4 112                  // window capacity: 112 float4 = 448 floats
#define NSTG  8                    // pipeline depth (buffers) = 2 quads
#define NSEN  64                   // sensors per CTA (half of 128)

__global__ void __launch_bounds__(256, 7)
das_main(const float* __restrict__ sd, const float* __restrict__ mask)
{
    __shared__ float win[NSTG][WCAP4 * 4];
    __shared__ __align__(16) float sxt[NSEN * 32];   // sx = max(rn(vx*vx), 1e-30)
    __shared__ float syt[NSEN * 32];                 // sy = rn(vy*vy) per (s, iy)
    __shared__ float smx[NSEN], smy[NSEN];
    __shared__ int   swb[NSEN], swn[NSEN];

    const int zb  = blockIdx.z;
    const int b   = zb >> 1;             // batch
    const int s_base = (zb & 1) << 6;    // sensor half: 0 or 64
    const int ix0 = blockIdx.x * 32;     // 0-based pixel tile origin
    const int iy0 = blockIdx.y * 32;
    const int tid = threadIdx.x;
    const int iy_off = tid & 31;         // this thread's iy within the tile
    const int ixg    = tid >> 5;         // ix group 0..7 (4 ix each)

    // packed constants for the f32x2 chain
    const uint32_t rvu = __float_as_uint(RCPVS);
    const uint32_t rdu = __float_as_uint(RCPDT);
    const uint64_t RCPVS2 = ((uint64_t)rvu << 32) | rvu;
    const uint64_t RCPDT2 = ((uint64_t)rdu << 32) | rdu;
    const uint64_t HALF2  = 0x3F0000003F000000ULL;   // {0.5f, 0.5f}
    const uint64_t SGN2   = 0x8000000080000000ULL;   // sign bits

    // ---- phase A: per-sensor coordinates + staging window bounds -----------
    if (tid < NSEN) {
        int sg = s_base + tid;
        float mxv = mask[((b * 128 + sg) << 1) + 0];
        float myv = mask[((b * 128 + sg) << 1) + 1];
        // separate mul then add (no FMA) — matches HLO mul + add
        float xm = __fadd_rn(__fmul_rn(mxv, 1000.0f), 128.0f);
        float ym = __fadd_rn(__fmul_rn(myv, 1000.0f), 128.0f);
        smx[tid] = xm;
        smy[tid] = ym;

        // corner (1-based) idx values of this tile
        float xl = (float)(ix0 + 1), xh = (float)(ix0 + 32);
        float yl = (float)(iy0 + 1), yh = (float)(iy0 + 32);

        // max distance over tile: at a corner (monotone exact chain per corner)
        float ax0 = __fadd_rn(__fsub_rn(xm, xl), 1.0f);
        float ax1 = __fadd_rn(__fsub_rn(xm, xh), 1.0f);
        float ay0 = __fadd_rn(__fsub_rn(ym, yl), 1.0f);
        float ay1 = __fadd_rn(__fsub_rn(ym, yh), 1.0f);
        float vx0 = __fmul_rn(ax0, DXc), vx1 = __fmul_rn(ax1, DXc);
        float vy0 = __fmul_rn(ay0, DYc), vy1 = __fmul_rn(ay1, DYc);
        float sx0 = __fmul_rn(vx0, vx0), sx1 = __fmul_rn(vx1, vx1);
        float sy0 = __fmul_rn(vy0, vy0), sy1 = __fmul_rn(vy1, vy1);
        float d2max = __fadd_rn(fmaxf(sx0, sx1), fmaxf(sy0, sy1));

        // min distance over tile: continuous clamp (lower bound), pad covers slop
        float ux = xm + 1.0f, uy = ym + 1.0f;   // sensor position in idx units
        float exd = fmaxf(fmaxf(xl - ux, ux - xh), 0.0f);
        float eyd = fmaxf(fmaxf(yl - uy, uy - yh), 0.0f);
        float vmx = exd * DXc, vmy = eyd * DYc;
        float d2min = vmx * vmx + vmy * vmy;

        int tmin = t_chain(d2min) - 8; if (tmin < 0) tmin = 0;
        int tmax = t_chain(d2max) + 8; if (tmax > 16383) tmax = 16383;

        int wb  = tmin & ~3;                       // 16B-aligned base
        int n4  = ((tmax - wb + 1) + 3) >> 2;      // float4 count
        int mx4 = (16384 - wb) >> 2;
        if (n4 > mx4)   n4 = mx4;
        if (n4 > WCAP4) n4 = WCAP4;                // provably never binds (<=97)
        swb[tid] = wb;
        swn[tid] = n4;
    }
    __syncthreads();

    // ---- phase B: precompute sx / sy term tables (exact chains) ------------
    #pragma unroll
    for (int i = tid; i < NSEN * 32; i += 256) {
        int s = i >> 5, l = i & 31;
        float xm  = smx[s], ym = smy[s];
        float ixf = (float)(ix0 + l + 1);
        float iyf = (float)(iy0 + l + 1);
        float ax  = __fadd_rn(__fsub_rn(xm, ixf), 1.0f);
        float vx  = __fmul_rn(ax, DXc);
        // clamp: changes d2 only when sx is 0/denormal, where t=0 either way.
        sxt[i] = fmaxf(__fmul_rn(vx, vx), 1e-30f);
        float ay  = __fadd_rn(__fsub_rn(ym, iyf), 1.0f);
        float vy  = __fmul_rn(ay, DYc);
        syt[i] = __fmul_rn(vy, vy);
    }
    __syncthreads();

    const float* row_base = sd + (size_t)b * 128 * 16384 + (size_t)s_base * 16384;
    const uint32_t sxt_base = (uint32_t)__cvta_generic_to_shared(sxt);

    auto stage = [&](int s) {   // caller guarantees tid < 128 (warps 0..3)
        const int bi = s & (NSTG - 1);
        int wb = swb[s];
        if (tid < swn[s]) {
            const float* g = row_base + (size_t)s * 16384 + wb + tid * 4;
            uint32_t sa = (uint32_t)__cvta_generic_to_shared(&win[bi][tid * 4]);
            asm volatile("cp.async.cg.shared.global [%0], [%1], 16;\n"
                         :: "r"(sa), "l"(g) : "memory");
        }
    };

    // prologue: stage quad 0 (sensors 0..3) as one group
    if (tid < 128) { stage(0); stage(1); stage(2); stage(3); }
    asm volatile("cp.async.commit_group;\n" ::: "memory");

    float acc0 = 0.0f, acc1 = 0.0f, acc2 = 0.0f, acc3 = 0.0f;

    for (int s = 0; s < NSEN; s += 4) {
        // one pending group at entry (quad s) — committed one full quad ago
        asm volatile("cp.async.wait_group 0;\n" ::: "memory");
        __syncthreads();   // quad s ready; everyone done reading quad s-1 buffers

        if (tid < 128) {
            if (s + 4 < NSEN) { stage(s + 4); stage(s + 5); stage(s + 6); stage(s + 7); }
        }
        asm volatile("cp.async.commit_group;\n" ::: "memory");  // keep count invariant

        #pragma unroll
        for (int j = 0; j < 4; ++j) {
            const int ss = s + j;
            const float* w = &win[ss & (NSTG - 1)][0] - swb[ss]; // pre-offset base
            float sy = syt[(ss << 5) + iy_off];                  // stride-1, no conflicts
            uint64_t sy2 = pack2(sy, sy);
            uint32_t sa = sxt_base + (ss << 7) + (ixg << 4);     // byte addr of sx pair
            uint64_t sx01, sx23;
            asm("ld.shared.b64 %0, [%1];" : "=l"(sx01) : "r"(sa));
            asm("ld.shared.b64 %0, [%1];" : "=l"(sx23) : "r"(sa + 8));

            int t0, t1, t2, t3;
            t2_fast(sx01, sy2, HALF2, SGN2, RCPVS2, RCPDT2, t0, t1);
            t2_fast(sx23, sy2, HALF2, SGN2, RCPVS2, RCPDT2, t2, t3);
            acc0 = __fadd_rn(acc0, w[t0]);
            acc1 = __fadd_rn(acc1, w[t1]);
            acc2 = __fadd_rn(acc2, w[t2]);
            acc3 = __fadd_rn(acc3, w[t3]);
        }
    }

    // write un-normalized partial sums: plane (half*8 + b)
    float* osc = g_scratch + ((zb & 1) * 8 + b) * 65536
               + (ix0 + ixg * 4) * 256 + iy0 + iy_off;
    osc[0]   = acc0;
    osc[256] = acc1;
    osc[512] = acc2;
    osc[768] = acc3;
}

// ---------------------------------------------------------------------------
// Kernel 2: per-(batch, chunk) partial min/max over plane0+plane1, coalesced.
// grid = 64 (8 batches x 8 chunks of 8192), 256 threads.
// ---------------------------------------------------------------------------
__global__ void __launch_bounds__(256)
das_minmax()
{
    __shared__ float rmn[256], rmx[256];
    const int b     = blockIdx.x >> 3;
    const int chunk = blockIdx.x & 7;
    const int tid   = threadIdx.x;
    const float* p0 = g_scratch + b * 65536 + chunk * 8192;
    const float* p1 = p0 + 8 * 65536;

    float mn =  3.402823466e38f;
    float mx = -3.402823466e38f;
    #pragma unroll 4
    for (int i = tid; i < 8192; i += 256) {
        float v = __fadd_rn(p0[i], p1[i]);
        mn = fminf(mn, v);
        mx = fmaxf(mx, v);
    }
    rmn[tid] = mn; rmx[tid] = mx;
    __syncthreads();
    for (int o = 128; o > 0; o >>= 1) {
        if (tid < o) {
            rmn[tid] = fminf(rmn[tid], rmn[tid + o]);
            rmx[tid] = fmaxf(rmx[tid], rmx[tid + o]);
        }
        __syncthreads();
    }
    if (tid == 0) { g_pmn[blockIdx.x] = rmn[0]; g_pmx[blockIdx.x] = rmx[0]; }
}

// ---------------------------------------------------------------------------
// Kernel 3: normalize + transpose via 32x32 smem tiles, coalesced both ways.
// grid = (64, 8): 64 tiles per batch. block 256 = 32x8.
// ---------------------------------------------------------------------------
__global__ void __launch_bounds__(256)
das_norm_t(float* __restrict__ out)
{
    __shared__ float tile[32][33];
    const int b  = blockIdx.y;
    const int tx = blockIdx.x & 7;   // ix tile
    const int ty = blockIdx.x >> 3;  // iy tile
    const int lx = threadIdx.x & 31;
    const int lr = threadIdx.x >> 5; // 0..7

    // reduce the 8 per-batch partials (redundant per CTA, trivial)
    float mn = g_pmn[b * 8 + 0], mx = g_pmx[b * 8 + 0];
    #pragma unroll
    for (int c = 1; c < 8; ++c) {
        mn = fminf(mn, g_pmn[b * 8 + c]);
        mx = fmaxf(mx, g_pmx[b * 8 + c]);
    }
    float den = __fsub_rn(mx, mn);

    const float* i0 = g_scratch + b * 65536;
    const float* i1 = i0 + 8 * 65536;
    // load: rows are ix (tx*32 + r), cols iy (ty*32 + lx) — coalesced
    #pragma unroll
    for (int r = lr; r < 32; r += 8) {
        int p = (tx * 32 + r) * 256 + ty * 32 + lx;
        tile[r][lx] = __fadd_rn(i0[p], i1[p]);   // same order as das_minmax
    }
    __syncthreads();

    float* ob = out + b * 65536;
    // store: out[b, iy, ix] — rows iy (ty*32 + r), cols ix (tx*32 + lx) — coalesced
    #pragma unroll
    for (int r = lr; r < 32; r += 8) {
        float v = tile[lx][r];
        ob[(ty * 32 + r) * 256 + tx * 32 + lx] = __fdiv_rn(__fsub_rn(v, mn), den);
    }
}

// ---------------------------------------------------------------------------
extern "C" void kernel_launch(void* const* d_in, const int* in_sizes, int n_in,
                              void* d_out, int out_size)
{
    const float* sd   = (const float*)d_in[0];   // (8,128,16384) f32
    const float* mask = (const float*)d_in[1];   // (8,128,2) f32
    float* out = (float*)d_out;                  // (8,256,256) f32

    // z = batch*2 + sensor-half: 1024 CTAs -> ~7/SM, single co-resident wave
    dim3 grid(8, 8, 16);
    das_main<<<grid, 256>>>(sd, mask);
    das_minmax<<<64, 256>>>();
    das_norm_t<<<dim3(64, 8), 256>>>(out);
}

// round 15
// speedup vs baseline: 3.4356x; 1.0067x over previous
#include <cuda_runtime.h>
#include <cstdint>

// ---------------------------------------------------------------------------
// DAS beamformer — replicates XLA's compiled f32 chain:
//   m  = rn(rn(mask*1000) + 128)                      (separate mul/add, no FMA)
//   vx = rn(rn(rn(x - idx) + 1) * DX);  sx = rn(vx*vx)
//   d2 = rn(sx + sy);  dis = sqrt.rn(d2)
//   t  = trunc( rn( rn(dis * rn(1/1500)) * 12500000.0f ) )
// (XLA algsimp rewrites divide-by-constant -> multiply-by-reciprocal.)
//   out[b, iy, ix] = (image - min_b) / (max_b - min_b)
// Inner loop: packed f32x2 chain (2 gathers per sequence). Per-component the
// ops are IEEE RN, identical to scalar. sqrt via RSQ + 1 Newton matches
// sqrt.rn except ~2^-20 probability 1-ulp cases (<0.1 expected flips total).
// ---------------------------------------------------------------------------

static constexpr float DXc   = 0.001f;
static constexpr float DYc   = 0.001f;
static constexpr float DTF   = (float)(1.0 / 12500000.0);
static constexpr float RCPVS = (float)(1.0 / 1500.0);          // rn(1/1500)
static constexpr float RCPDT = (float)(1.0 / (double)DTF);     // == 12500000.0f

// scratch: four sensor-quarter planes of un-normalized sums.
// plane (q*8 + b), pixel p = ix*256 + iy. Final image = (p0+p1)+(p2+p3).
__device__ float g_scratch[32 * 65536];
__device__ float g_pmn[64], g_pmx[64];   // per-(batch, chunk) partial min/max

// exact chain (used for window bounds only)
__device__ __forceinline__ int t_chain(float d2) {
    float dis = __fsqrt_rn(d2);
    float q1  = __fmul_rn(dis, RCPVS);
    float q2  = __fmul_rn(q1, RCPDT);
    return __float2int_rz(q2);
}

__device__ __forceinline__ uint64_t pack2(float a, float b) {
    uint64_t v; asm("mov.b64 %0, {%1, %2};" : "=l"(v) : "f"(a), "f"(b)); return v;
}

// Packed 2-wide t computation: d2 = sx + sy; dis = RSQ+Newton sqrt;
// t = trunc(dis * RCPVS * RCPDT). All packed ops are per-component IEEE RN.
// Caller guarantees d2 > 0 (sxt table is clamped to >= 1e-30).
__device__ __forceinline__ void t2_fast(uint64_t sx2, uint64_t sy2,
                                        uint64_t half2, uint64_t sgn2,
                                        uint64_t rcpvs2, uint64_t rcpdt2,
                                        int &ta, int &tb)
{
    asm("{\n\t"
        ".reg .f32 lo, hi, rl, rh, qa, qb;\n\t"
        ".reg .b64 d2, r2, y2, h2, e2, ds, p1, p2, yn;\n\t"
        "add.rn.f32x2 d2, %2, %3;\n\t"
        "mov.b64 {lo, hi}, d2;\n\t"
        "rsqrt.approx.f32 rl, lo;\n\t"
        "rsqrt.approx.f32 rh, hi;\n\t"
        "mov.b64 r2, {rl, rh};\n\t"
        "mul.rn.f32x2 y2, d2, r2;\n\t"
        "mul.rn.f32x2 h2, r2, %4;\n\t"
        "xor.b64 yn, y2, %5;\n\t"
        "fma.rn.f32x2 e2, yn, y2, d2;\n\t"
        "fma.rn.f32x2 ds, e2, h2, y2;\n\t"
        "mul.rn.f32x2 p1, ds, %6;\n\t"
        "mul.rn.f32x2 p2, p1, %7;\n\t"
        "mov.b64 {qa, qb}, p2;\n\t"
        "cvt.rzi.s32.f32 %0, qa;\n\t"
        "cvt.rzi.s32.f32 %1, qb;\n\t"
        "}"
        : "=r"(ta), "=r"(tb)
        : "l"(sx2), "l"(sy2), "l"(half2), "l"(sgn2),
          "l"(rcpvs2), "l"(rcpdt2));
}

// ---------------------------------------------------------------------------
// Kernel 1: per-CTA 32x32 pixel tile x 32-sensor quarter, 256 threads.
// Quad-unrolled sensor loop: one barrier / one cp.async group per 4 sensors,
// 8 window buffers (staging quad q+1 while computing quad q).
// Window range for a 32x32 tile <= 31*sqrt(2)*DX/VS/DT (365.4) + 16 pad + 3
// align < 448 floats, so WCAP4=112 provably covers every gather (the pad also
// absorbs the <=1-ulp t difference between fast and exact chains).
// ---------------------------------------------------------------------------
#define WCAP4 112                  // window capacity: 112 float4 = 448 floats
#define NSTG  8                    // pipeline depth (buffers) = 2 quads
#define NSEN  32                   // sensors per CTA (quarter of 128)

__global__ void __launch_bounds__(256, 7)
das_main(const float* __restrict__ sd, const float* __restrict__ mask)
{
    __shared__ float win[NSTG][WCAP4 * 4];
    __shared__ __align__(16) float sxt[NSEN * 32];   // sx = max(rn(vx*vx), 1e-30)
    __shared__ float syt[NSEN * 32];                 // sy = rn(vy*vy) per (s, iy)
    __shared__ float smx[NSEN], smy[NSEN];
    __shared__ int   swb[NSEN], swn[NSEN];

    const int zb  = blockIdx.z;
    const int b   = zb >> 2;             // batch
    const int qtr = zb & 3;              // sensor quarter 0..3
    const int s_base = qtr << 5;         // sensor base: 0,32,64,96
    const int ix0 = blockIdx.x * 32;     // 0-based pixel tile origin
    const int iy0 = blockIdx.y * 32;
    const int tid = threadIdx.x;
    const int iy_off = tid & 31;         // this thread's iy within the tile
    const int ixg    = tid >> 5;         // ix group 0..7 (4 ix each)

    // packed constants for the f32x2 chain
    const uint32_t rvu = __float_as_uint(RCPVS);
    const uint32_t rdu = __float_as_uint(RCPDT);
    const uint64_t RCPVS2 = ((uint64_t)rvu << 32) | rvu;
    const uint64_t RCPDT2 = ((uint64_t)rdu << 32) | rdu;
    const uint64_t HALF2  = 0x3F0000003F000000ULL;   // {0.5f, 0.5f}
    const uint64_t SGN2   = 0x8000000080000000ULL;   // sign bits

    // ---- phase A: per-sensor coordinates + staging window bounds -----------
    if (tid < NSEN) {
        int sg = s_base + tid;
        float mxv = mask[((b * 128 + sg) << 1) + 0];
        float myv = mask[((b * 128 + sg) << 1) + 1];
        // separate mul then add (no FMA) — matches HLO mul + add
        float xm = __fadd_rn(__fmul_rn(mxv, 1000.0f), 128.0f);
        float ym = __fadd_rn(__fmul_rn(myv, 1000.0f), 128.0f);
        smx[tid] = xm;
        smy[tid] = ym;

        // corner (1-based) idx values of this tile
        float xl = (float)(ix0 + 1), xh = (float)(ix0 + 32);
        float yl = (float)(iy0 + 1), yh = (float)(iy0 + 32);

        // max distance over tile: at a corner (monotone exact chain per corner)
        float ax0 = __fadd_rn(__fsub_rn(xm, xl), 1.0f);
        float ax1 = __fadd_rn(__fsub_rn(xm, xh), 1.0f);
        float ay0 = __fadd_rn(__fsub_rn(ym, yl), 1.0f);
        float ay1 = __fadd_rn(__fsub_rn(ym, yh), 1.0f);
        float vx0 = __fmul_rn(ax0, DXc), vx1 = __fmul_rn(ax1, DXc);
        float vy0 = __fmul_rn(ay0, DYc), vy1 = __fmul_rn(ay1, DYc);
        float sx0 = __fmul_rn(vx0, vx0), sx1 = __fmul_rn(vx1, vx1);
        float sy0 = __fmul_rn(vy0, vy0), sy1 = __fmul_rn(vy1, vy1);
        float d2max = __fadd_rn(fmaxf(sx0, sx1), fmaxf(sy0, sy1));

        // min distance over tile: continuous clamp (lower bound), pad covers slop
        float ux = xm + 1.0f, uy = ym + 1.0f;   // sensor position in idx units
        float exd = fmaxf(fmaxf(xl - ux, ux - xh), 0.0f);
        float eyd = fmaxf(fmaxf(yl - uy, uy - yh), 0.0f);
        float vmx = exd * DXc, vmy = eyd * DYc;
        float d2min = vmx * vmx + vmy * vmy;

        int tmin = t_chain(d2min) - 8; if (tmin < 0) tmin = 0;
        int tmax = t_chain(d2max) + 8; if (tmax > 16383) tmax = 16383;

        int wb  = tmin & ~3;                       // 16B-aligned base
        int n4  = ((tmax - wb + 1) + 3) >> 2;      // float4 count
        int mx4 = (16384 - wb) >> 2;
        if (n4 > mx4)   n4 = mx4;
        if (n4 > WCAP4) n4 = WCAP4;                // provably never binds (<=97)
        swb[tid] = wb;
        swn[tid] = n4;
    }
    __syncthreads();

    // ---- phase B: precompute sx / sy term tables (exact chains) ------------
    #pragma unroll
    for (int i = tid; i < NSEN * 32; i += 256) {
        int s = i >> 5, l = i & 31;
        float xm  = smx[s], ym = smy[s];
        float ixf = (float)(ix0 + l + 1);
        float iyf = (float)(iy0 + l + 1);
        float ax  = __fadd_rn(__fsub_rn(xm, ixf), 1.0f);
        float vx  = __fmul_rn(ax, DXc);
        // clamp: changes d2 only when sx is 0/denormal, where t=0 either way.
        sxt[i] = fmaxf(__fmul_rn(vx, vx), 1e-30f);
        float ay  = __fadd_rn(__fsub_rn(ym, iyf), 1.0f);
        float vy  = __fmul_rn(ay, DYc);
        syt[i] = __fmul_rn(vy, vy);
    }
    __syncthreads();

    const float* row_base = sd + (size_t)b * 128 * 16384 + (size_t)s_base * 16384;
    const uint32_t sxt_base = (uint32_t)__cvta_generic_to_shared(sxt);

    auto stage = [&](int s) {   // caller guarantees tid < 128 (warps 0..3)
        const int bi = s & (NSTG - 1);
        int wb = swb[s];
        if (tid < swn[s]) {
            const float* g = row_base + (size_t)s * 16384 + wb + tid * 4;
            uint32_t sa = (uint32_t)__cvta_generic_to_shared(&win[bi][tid * 4]);
            asm volatile("cp.async.cg.shared.global [%0], [%1], 16;\n"
                         :: "r"(sa), "l"(g) : "memory");
        }
    };

    // prologue: stage quad 0 (sensors 0..3) as one group
    if (tid < 128) { stage(0); stage(1); stage(2); stage(3); }
    asm volatile("cp.async.commit_group;\n" ::: "memory");

    float acc0 = 0.0f, acc1 = 0.0f, acc2 = 0.0f, acc3 = 0.0f;

    for (int s = 0; s < NSEN; s += 4) {
        // one pending group at entry (quad s) — committed one full quad ago
        asm volatile("cp.async.wait_group 0;\n" ::: "memory");
        __syncthreads();   // quad s ready; everyone done reading quad s-1 buffers

        if (tid < 128) {
            if (s + 4 < NSEN) { stage(s + 4); stage(s + 5); stage(s + 6); stage(s + 7); }
        }
        asm volatile("cp.async.commit_group;\n" ::: "memory");  // keep count invariant

        #pragma unroll
        for (int j = 0; j < 4; ++j) {
            const int ss = s + j;
            const float* w = &win[ss & (NSTG - 1)][0] - swb[ss]; // pre-offset base
            float sy = syt[(ss << 5) + iy_off];                  // stride-1, no conflicts
            uint64_t sy2 = pack2(sy, sy);
            uint32_t sa = sxt_base + (ss << 7) + (ixg << 4);     // byte addr of sx pair
            uint64_t sx01, sx23;
            asm("ld.shared.b64 %0, [%1];" : "=l"(sx01) : "r"(sa));
            asm("ld.shared.b64 %0, [%1];" : "=l"(sx23) : "r"(sa + 8));

            int t0, t1, t2, t3;
            t2_fast(sx01, sy2, HALF2, SGN2, RCPVS2, RCPDT2, t0, t1);
            t2_fast(sx23, sy2, HALF2, SGN2, RCPVS2, RCPDT2, t2, t3);
            acc0 = __fadd_rn(acc0, w[t0]);
            acc1 = __fadd_rn(acc1, w[t1]);
            acc2 = __fadd_rn(acc2, w[t2]);
            acc3 = __fadd_rn(acc3, w[t3]);
        }
    }

    // write un-normalized partial sums: plane (quarter*8 + b)
    float* osc = g_scratch + (qtr * 8 + b) * 65536
               + (ix0 + ixg * 4) * 256 + iy0 + iy_off;
    osc[0]   = acc0;
    osc[256] = acc1;
    osc[512] = acc2;
    osc[768] = acc3;
}

// ---------------------------------------------------------------------------
// Kernel 2: per-(batch, chunk) partial min/max over 4 planes, coalesced.
// grid = 64 (8 batches x 8 chunks of 8192), 256 threads.
// ---------------------------------------------------------------------------
__global__ void __launch_bounds__(256)
das_minmax()
{
    __shared__ float rmn[256], rmx[256];
    const int b     = blockIdx.x >> 3;
    const int chunk = blockIdx.x & 7;
    const int tid   = threadIdx.x;
    const float* p0 = g_scratch + b * 65536 + chunk * 8192;
    const float* p1 = p0 + 8 * 65536;
    const float* p2 = p0 + 16 * 65536;
    const float* p3 = p0 + 24 * 65536;

    float mn =  3.402823466e38f;
    float mx = -3.402823466e38f;
    #pragma unroll 4
    for (int i = tid; i < 8192; i += 256) {
        float v = __fadd_rn(__fadd_rn(p0[i], p1[i]), __fadd_rn(p2[i], p3[i]));
        mn = fminf(mn, v);
        mx = fmaxf(mx, v);
    }
    rmn[tid] = mn; rmx[tid] = mx;
    __syncthreads();
    for (int o = 128; o > 0; o >>= 1) {
        if (tid < o) {
            rmn[tid] = fminf(rmn[tid], rmn[tid + o]);
            rmx[tid] = fmaxf(rmx[tid], rmx[tid + o]);
        }
        __syncthreads();
    }
    if (tid == 0) { g_pmn[blockIdx.x] = rmn[0]; g_pmx[blockIdx.x] = rmx[0]; }
}

// ---------------------------------------------------------------------------
// Kernel 3: normalize + transpose via 32x32 smem tiles, coalesced both ways.
// grid = (64, 8): 64 tiles per batch. block 256 = 32x8.
// ---------------------------------------------------------------------------
__global__ void __launch_bounds__(256)
das_norm_t(float* __restrict__ out)
{
    __shared__ float tile[32][33];
    const int b  = blockIdx.y;
    const int tx = blockIdx.x & 7;   // ix tile
    const int ty = blockIdx.x >> 3;  // iy tile
    const int lx = threadIdx.x & 31;
    const int lr = threadIdx.x >> 5; // 0..7

    // reduce the 8 per-batch partials (redundant per CTA, trivial)
    float mn = g_pmn[b * 8 + 0], mx = g_pmx[b * 8 + 0];
    #pragma unroll
    for (int c = 1; c < 8; ++c) {
        mn = fminf(mn, g_pmn[b * 8 + c]);
        mx = fmaxf(mx, g_pmx[b * 8 + c]);
    }
    float den = __fsub_rn(mx, mn);

    const float* i0 = g_scratch + b * 65536;
    const float* i1 = i0 + 8 * 65536;
    const float* i2 = i0 + 16 * 65536;
    const float* i3 = i0 + 24 * 65536;
    // load: rows are ix (tx*32 + r), cols iy (ty*32 + lx) — coalesced
    #pragma unroll
    for (int r = lr; r < 32; r += 8) {
        int p = (tx * 32 + r) * 256 + ty * 32 + lx;
        // same association as das_minmax
        tile[r][lx] = __fadd_rn(__fadd_rn(i0[p], i1[p]), __fadd_rn(i2[p], i3[p]));
    }
    __syncthreads();

    float* ob = out + b * 65536;
    // store: out[b, iy, ix] — rows iy (ty*32 + r), cols ix (tx*32 + lx) — coalesced
    #pragma unroll
    for (int r = lr; r < 32; r += 8) {
        float v = tile[lx][r];
        ob[(ty * 32 + r) * 256 + tx * 32 + lx] = __fdiv_rn(__fsub_rn(v, mn), den);
    }
}

// ---------------------------------------------------------------------------
extern "C" void kernel_launch(void* const* d_in, const int* in_sizes, int n_in,
                              void* d_out, int out_size)
{
    const float* sd   = (const float*)d_in[0];   // (8,128,16384) f32
    const float* mask = (const float*)d_in[1];   // (8,128,2) f32
    float* out = (float*)d_out;                  // (8,256,256) f32

    // z = batch*4 + sensor-quarter: 2048 CTAs -> two near-perfect waves of 7/SM
    dim3 grid(8, 8, 32);
    das_main<<<grid, 256>>>(sd, mask);
    das_minmax<<<64, 256>>>();
    das_norm_t<<<dim3(64, 8), 256>>>(out);
}